// round 5
// baseline (speedup 1.0000x reference)
#include <cuda_runtime.h>
#include <cstddef>

// ---------------------------------------------------------------------------
// VQ-VAE forward. Numerical contract: faithful fp32 everywhere.
//  - GEMMs: per-element single accumulator, k ascending, fused FMA (frozen:
//    bit-matches reference z — do not change for encoder path)
//  - A = sum z^2: strided-pair warp tree: lane l -> fl(z[l]^2)+fl(z[l+32]^2),
//    shfl-down tree 16,8,4,2,1            [redrawn this round]
//  - B = sum e^2: consecutive-pair warp tree (R3)
//  - E = z.e: half-split fused: fl(sum_{d<32} fma + sum_{d>=32} fma)
//                                          [redrawn this round]
//  - dist = fl(fl(A+B) - 2E), argmin first-index tie-break
// ---------------------------------------------------------------------------

#define B_      8192
#define IN_DIM  1024
#define HID     2048
#define KCODES  512
#define DDIM    64
#define LLAT    32

__device__ float g_h [(size_t)B_ * HID];
__device__ float g_h2[(size_t)B_ * HID];
__device__ float g_Bk[KCODES];

// ---------------------------------------------------------------------------
__global__ void bk_kernel(const float* __restrict__ emb, float* __restrict__ Bk)
{
    int gwarp = (blockIdx.x * blockDim.x + threadIdx.x) >> 5;
    int lane  = threadIdx.x & 31;
    if (gwarp < KCODES) {
        const float* e = emb + (size_t)gwarp * DDIM;
        float e0 = e[2 * lane], e1 = e[2 * lane + 1];
        float p = __fadd_rn(__fmul_rn(e0, e0), __fmul_rn(e1, e1));
        #pragma unroll
        for (int off = 16; off > 0; off >>= 1)
            p = __fadd_rn(p, __shfl_down_sync(0xffffffffu, p, off));
        if (lane == 0) Bk[gwarp] = p;
    }
}

// ---------------------------------------------------------------------------
// SGEMM: frozen numerics (k ascending, fused fma, single accumulator).
// ---------------------------------------------------------------------------
template<bool RELU>
__global__ __launch_bounds__(256, 2)
void sgemm(const float* __restrict__ A, const float* __restrict__ W,
           const float* __restrict__ bias, float* __restrict__ C,
           int M, int N, int K)
{
    __shared__ float As[8][128];
    __shared__ float Bs[8][128];

    const int tid = threadIdx.x;
    const int bm = blockIdx.y * 128;
    const int bn = blockIdx.x * 128;

    const int arow = tid >> 1;
    const int acol = (tid & 1) * 4;
    const int wrow = tid >> 5;
    const int wcol = (tid & 31) * 4;

    const int tx = tid & 15;
    const int ty = tid >> 4;

    float acc[8][8];
    #pragma unroll
    for (int i = 0; i < 8; i++)
        #pragma unroll
        for (int j = 0; j < 8; j++) acc[i][j] = 0.f;

    const float* Aptr = A + (size_t)(bm + arow) * K + acol;
    const float* Wptr = W + (size_t)wrow * N + bn + wcol;

    for (int k0 = 0; k0 < K; k0 += 8) {
        float4 av = *(const float4*)(Aptr + k0);
        float4 wv = *(const float4*)(Wptr + (size_t)k0 * N);
        __syncthreads();
        As[acol + 0][arow] = av.x;
        As[acol + 1][arow] = av.y;
        As[acol + 2][arow] = av.z;
        As[acol + 3][arow] = av.w;
        *(float4*)&Bs[wrow][wcol] = wv;
        __syncthreads();

        #pragma unroll
        for (int kk = 0; kk < 8; kk++) {
            float a[8], b[8];
            *(float4*)&a[0] = *(const float4*)&As[kk][ty * 8];
            *(float4*)&a[4] = *(const float4*)&As[kk][ty * 8 + 4];
            *(float4*)&b[0] = *(const float4*)&Bs[kk][tx * 8];
            *(float4*)&b[4] = *(const float4*)&Bs[kk][tx * 8 + 4];
            #pragma unroll
            for (int i = 0; i < 8; i++)
                #pragma unroll
                for (int j = 0; j < 8; j++)
                    acc[i][j] = fmaf(a[i], b[j], acc[i][j]);
        }
    }

    float bb[8];
    *(float4*)&bb[0] = *(const float4*)(bias + bn + tx * 8);
    *(float4*)&bb[4] = *(const float4*)(bias + bn + tx * 8 + 4);

    #pragma unroll
    for (int i = 0; i < 8; i++) {
        size_t row = (size_t)(bm + ty * 8 + i);
        float* cp = C + row * N + bn + tx * 8;
        float4 v0, v1;
        v0.x = __fadd_rn(acc[i][0], bb[0]); v0.y = __fadd_rn(acc[i][1], bb[1]);
        v0.z = __fadd_rn(acc[i][2], bb[2]); v0.w = __fadd_rn(acc[i][3], bb[3]);
        v1.x = __fadd_rn(acc[i][4], bb[4]); v1.y = __fadd_rn(acc[i][5], bb[5]);
        v1.z = __fadd_rn(acc[i][6], bb[6]); v1.w = __fadd_rn(acc[i][7], bb[7]);
        if (RELU) {
            v0.x = fmaxf(v0.x, 0.f); v0.y = fmaxf(v0.y, 0.f);
            v0.z = fmaxf(v0.z, 0.f); v0.w = fmaxf(v0.w, 0.f);
            v1.x = fmaxf(v1.x, 0.f); v1.y = fmaxf(v1.y, 0.f);
            v1.z = fmaxf(v1.z, 0.f); v1.w = fmaxf(v1.w, 0.f);
        }
        *(float4*)cp = v0;
        *(float4*)(cp + 4) = v1;
    }
}

// ---------------------------------------------------------------------------
// VQ kernel. A: strided-pair tree (new draw). E: half-split fused (new draw).
// ---------------------------------------------------------------------------
__global__ __launch_bounds__(256)
void vq_kernel(const float* __restrict__ Z, const float* __restrict__ emb,
               const float* __restrict__ Bk,
               float* __restrict__ zq, float* __restrict__ idx_out)
{
    __shared__ float z_s[32][DDIM];       // 8 KB
    __shared__ float e_s[DDIM][128];      // 32 KB
    __shared__ float bk_s[128];

    const int tid  = threadIdx.x;
    const int lane = tid & 31;
    const int warp = tid >> 5;
    const size_t row0 = (size_t)blockIdx.x * 32;
    const int r0 = warp * 4;

    {
        const float4* zg = (const float4*)(Z + row0 * DDIM);
        float4* zs = (float4*)z_s;
        zs[tid]       = zg[tid];
        zs[tid + 256] = zg[tid + 256];
    }
    __syncthreads();

    // A per row: strided pairs (lane l: d=l and d=l+32), then shfl tree.
    float Ar[4];
    #pragma unroll
    for (int rr = 0; rr < 4; rr++) {
        const float* zp = z_s[r0 + rr];
        float z0 = zp[lane], z1 = zp[lane + 32];
        float p = __fadd_rn(__fmul_rn(z0, z0), __fmul_rn(z1, z1));
        #pragma unroll
        for (int off = 16; off > 0; off >>= 1)
            p = __fadd_rn(p, __shfl_down_sync(0xffffffffu, p, off));
        Ar[rr] = __shfl_sync(0xffffffffu, p, 0);
    }

    float best_d[4];
    int   best_k[4];
    #pragma unroll
    for (int r = 0; r < 4; r++) { best_d[r] = 3.4e38f; best_k[r] = 0; }

    for (int c0 = 0; c0 < KCODES; c0 += 128) {
        __syncthreads();
        {
            int kk = tid >> 1;
            int d0 = (tid & 1) * 32;
            const float* ep = emb + (size_t)(c0 + kk) * DDIM + d0;
            #pragma unroll
            for (int i = 0; i < 32; i += 4) {
                float4 v = *(const float4*)(ep + i);
                e_s[d0 + i + 0][kk] = v.x;
                e_s[d0 + i + 1][kk] = v.y;
                e_s[d0 + i + 2][kk] = v.z;
                e_s[d0 + i + 3][kk] = v.w;
            }
            if (tid < 128) bk_s[tid] = Bk[c0 + tid];
        }
        __syncthreads();

        float accL[4][4], accH[4][4];
        #pragma unroll
        for (int r = 0; r < 4; r++)
            #pragma unroll
            for (int s = 0; s < 4; s++) { accL[r][s] = 0.f; accH[r][s] = 0.f; }

        // E half-split: low half d=0..31 fused, high half d=32..63 fused
        #pragma unroll 8
        for (int d = 0; d < DDIM / 2; d++) {
            float zv[4], ev[4];
            #pragma unroll
            for (int r = 0; r < 4; r++) zv[r] = z_s[r0 + r][d];
            #pragma unroll
            for (int s = 0; s < 4; s++) ev[s] = e_s[d][s * 32 + lane];
            #pragma unroll
            for (int r = 0; r < 4; r++)
                #pragma unroll
                for (int s = 0; s < 4; s++)
                    accL[r][s] = fmaf(zv[r], ev[s], accL[r][s]);
        }
        #pragma unroll 8
        for (int d = DDIM / 2; d < DDIM; d++) {
            float zv[4], ev[4];
            #pragma unroll
            for (int r = 0; r < 4; r++) zv[r] = z_s[r0 + r][d];
            #pragma unroll
            for (int s = 0; s < 4; s++) ev[s] = e_s[d][s * 32 + lane];
            #pragma unroll
            for (int r = 0; r < 4; r++)
                #pragma unroll
                for (int s = 0; s < 4; s++)
                    accH[r][s] = fmaf(zv[r], ev[s], accH[r][s]);
        }

        #pragma unroll
        for (int r = 0; r < 4; r++) {
            #pragma unroll
            for (int s = 0; s < 4; s++) {
                int k = c0 + s * 32 + lane;
                float E  = __fadd_rn(accL[r][s], accH[r][s]);
                float t  = __fadd_rn(Ar[r], bk_s[s * 32 + lane]);
                float ds = __fadd_rn(t, -2.0f * E);
                if (ds < best_d[r]) { best_d[r] = ds; best_k[r] = k; }
            }
        }
    }

    #pragma unroll
    for (int r = 0; r < 4; r++) {
        float bd = best_d[r];
        int   bk = best_k[r];
        #pragma unroll
        for (int off = 16; off > 0; off >>= 1) {
            float od = __shfl_down_sync(0xffffffffu, bd, off);
            int   ok = __shfl_down_sync(0xffffffffu, bk, off);
            if (od < bd || (od == bd && ok < bk)) { bd = od; bk = ok; }
        }
        bk = __shfl_sync(0xffffffffu, bk, 0);

        size_t grow = row0 + (size_t)warp * 4 + r;
        zq[grow * DDIM + lane]      = emb[(size_t)bk * DDIM + lane];
        zq[grow * DDIM + 32 + lane] = emb[(size_t)bk * DDIM + 32 + lane];
        if (lane == 0) idx_out[grow] = (float)bk;
    }
}

// ---------------------------------------------------------------------------
extern "C" void kernel_launch(void* const* d_in, const int* in_sizes, int n_in,
                              void* d_out, int out_size)
{
    const float* x   = (const float*)d_in[0];
    const float* W1  = (const float*)d_in[1];
    const float* b1  = (const float*)d_in[2];
    const float* W2  = (const float*)d_in[3];
    const float* b2  = (const float*)d_in[4];
    const float* emb = (const float*)d_in[5];
    const float* W3  = (const float*)d_in[6];
    const float* b3  = (const float*)d_in[7];
    const float* W4  = (const float*)d_in[8];
    const float* b4  = (const float*)d_in[9];

    float* out     = (float*)d_out;
    float* x_recon = out;
    float* z       = out + (size_t)B_ * IN_DIM;
    float* zq      = z   + (size_t)B_ * (LLAT * DDIM);
    float* idxf    = zq  + (size_t)B_ * (LLAT * DDIM);

    float *h, *h2, *Bk;
    cudaGetSymbolAddress((void**)&h,  g_h);
    cudaGetSymbolAddress((void**)&h2, g_h2);
    cudaGetSymbolAddress((void**)&Bk, g_Bk);

    bk_kernel<<<(KCODES * 32 + 255) / 256, 256>>>(emb, Bk);

    sgemm<true ><<<dim3(HID    / 128, B_ / 128), 256>>>(x,  W1, b1, h,       B_, HID,    IN_DIM);
    sgemm<false><<<dim3(HID    / 128, B_ / 128), 256>>>(h,  W2, b2, z,       B_, HID,    HID);
    vq_kernel<<<(B_ * LLAT) / 32, 256>>>(z, emb, Bk, zq, idxf);
    sgemm<true ><<<dim3(HID    / 128, B_ / 128), 256>>>(zq, W3, b3, h2,      B_, HID,    HID);
    sgemm<false><<<dim3(IN_DIM / 128, B_ / 128), 256>>>(h2, W4, b4, x_recon, B_, IN_DIM, HID);
}

// round 6
// speedup vs baseline: 1.1129x; 1.1129x over previous
#include <cuda_runtime.h>
#include <cstddef>

// ---------------------------------------------------------------------------
// VQ-VAE forward. NUMERICS FROZEN (bit-exact vs reference, rel_err==0.0):
//  - GEMMs: per-element single accumulator, k ascending, fused FMA.
//    This round: same math via fma.rn.f32x2 (each half independent IEEE rn
//    fp32 FMA -> bit-identical), double-buffered smem.
//  - A = sum z^2: strided-pair warp tree (lane l: z[l]^2 + z[l+32]^2, shfl
//    tree 16..1)   [FROZEN]
//  - B = sum e^2: consecutive-pair warp tree  [FROZEN]
//  - E = z.e: half-split fused (d<32 | d>=32)  [FROZEN]
//  - dist = fl(fl(A+B) - 2E), argmin first-index tie-break  [FROZEN]
// ---------------------------------------------------------------------------

#define B_      8192
#define IN_DIM  1024
#define HID     2048
#define KCODES  512
#define DDIM    64
#define LLAT    32

typedef unsigned long long ull;

__device__ float g_h [(size_t)B_ * HID];
__device__ float g_h2[(size_t)B_ * HID];
__device__ float g_Bk[KCODES];

// packed f32x2 helpers (sm_103a FFMA2 path; each lane is IEEE rn fp32)
__device__ __forceinline__ ull pack_dup(unsigned u) {
    ull r;
    asm("mov.b64 %0, {%1, %1};" : "=l"(r) : "r"(u));
    return r;
}
__device__ __forceinline__ void ffma2(ull& acc, ull a, ull b) {
    asm("fma.rn.f32x2 %0, %1, %2, %0;" : "+l"(acc) : "l"(a), "l"(b));
}

// ---------------------------------------------------------------------------
__global__ void bk_kernel(const float* __restrict__ emb, float* __restrict__ Bk)
{
    int gwarp = (blockIdx.x * blockDim.x + threadIdx.x) >> 5;
    int lane  = threadIdx.x & 31;
    if (gwarp < KCODES) {
        const float* e = emb + (size_t)gwarp * DDIM;
        float e0 = e[2 * lane], e1 = e[2 * lane + 1];
        float p = __fadd_rn(__fmul_rn(e0, e0), __fmul_rn(e1, e1));
        #pragma unroll
        for (int off = 16; off > 0; off >>= 1)
            p = __fadd_rn(p, __shfl_down_sync(0xffffffffu, p, off));
        if (lane == 0) Bk[gwarp] = p;
    }
}

// ---------------------------------------------------------------------------
// SGEMM via FFMA2: C = op(A @ W + bias). 128x128 tile, BK=8, 256 thr,
// 8x8 microtile packed as 4 row-pairs x 8 cols. Double-buffered smem.
// Per-element numerics identical to scalar fmaf k-ascending. DO NOT REORDER.
// ---------------------------------------------------------------------------
template<bool RELU>
__global__ __launch_bounds__(256, 2)
void sgemm(const float* __restrict__ A, const float* __restrict__ W,
           const float* __restrict__ bias, float* __restrict__ C,
           int M, int N, int K)
{
    __shared__ __align__(16) float As[2][8][128];   // As[buf][k][m]
    __shared__ __align__(16) float Bs[2][8][128];   // Bs[buf][k][n]

    const int tid = threadIdx.x;
    const int bm = blockIdx.y * 128;
    const int bn = blockIdx.x * 128;

    const int arow = tid >> 1;            // 0..127
    const int acol = (tid & 1) * 4;       // 0 or 4
    const int wrow = tid >> 5;            // 0..7
    const int wcol = (tid & 31) * 4;      // 0..124

    const int tx = tid & 15;              // N microtile
    const int ty = tid >> 4;              // M microtile

    ull acc2[4][8];                       // row-pairs (2i2,2i2+1) x 8 cols
    #pragma unroll
    for (int i = 0; i < 4; i++)
        #pragma unroll
        for (int j = 0; j < 8; j++) acc2[i][j] = 0ull;

    const float* Aptr = A + (size_t)(bm + arow) * K + acol;
    const float* Wptr = W + (size_t)wrow * N + bn + wcol;

    const int nt = K >> 3;

    // prologue: tile 0 -> buf 0
    float4 av = *(const float4*)(Aptr);
    float4 wv = *(const float4*)(Wptr);
    As[0][acol + 0][arow] = av.x;
    As[0][acol + 1][arow] = av.y;
    As[0][acol + 2][arow] = av.z;
    As[0][acol + 3][arow] = av.w;
    *(float4*)&Bs[0][wrow][wcol] = wv;
    __syncthreads();

    for (int t = 0; t < nt; t++) {
        const int cur = t & 1;
        if (t + 1 < nt) {
            av = *(const float4*)(Aptr + (t + 1) * 8);
            wv = *(const float4*)(Wptr + (size_t)(t + 1) * 8 * N);
        }

        #pragma unroll
        for (int kk = 0; kk < 8; kk++) {
            ull a2[4];
            const ull* ap = (const ull*)&As[cur][kk][ty * 8];
            a2[0] = ap[0]; a2[1] = ap[1]; a2[2] = ap[2]; a2[3] = ap[3];

            uint4 bv0 = *(const uint4*)&Bs[cur][kk][tx * 8];
            uint4 bv1 = *(const uint4*)&Bs[cur][kk][tx * 8 + 4];
            ull bd[8];
            bd[0] = pack_dup(bv0.x); bd[1] = pack_dup(bv0.y);
            bd[2] = pack_dup(bv0.z); bd[3] = pack_dup(bv0.w);
            bd[4] = pack_dup(bv1.x); bd[5] = pack_dup(bv1.y);
            bd[6] = pack_dup(bv1.z); bd[7] = pack_dup(bv1.w);

            #pragma unroll
            for (int i = 0; i < 4; i++)
                #pragma unroll
                for (int j = 0; j < 8; j++)
                    ffma2(acc2[i][j], a2[i], bd[j]);
        }

        if (t + 1 < nt) {
            const int nxt = cur ^ 1;
            As[nxt][acol + 0][arow] = av.x;
            As[nxt][acol + 1][arow] = av.y;
            As[nxt][acol + 2][arow] = av.z;
            As[nxt][acol + 3][arow] = av.w;
            *(float4*)&Bs[nxt][wrow][wcol] = wv;
            __syncthreads();
        }
    }

    // epilogue: unpack, + bias (__fadd_rn), optional relu, float4 stores
    float bb[8];
    *(float4*)&bb[0] = *(const float4*)(bias + bn + tx * 8);
    *(float4*)&bb[4] = *(const float4*)(bias + bn + tx * 8 + 4);

    #pragma unroll
    for (int i2 = 0; i2 < 4; i2++) {
        float lo[8], hi[8];
        #pragma unroll
        for (int j = 0; j < 8; j++) {
            lo[j] = __uint_as_float((unsigned)(acc2[i2][j]));
            hi[j] = __uint_as_float((unsigned)(acc2[i2][j] >> 32));
        }
        #pragma unroll
        for (int half = 0; half < 2; half++) {
            const float* accr = half ? hi : lo;
            size_t row = (size_t)(bm + ty * 8 + i2 * 2 + half);
            float* cp = C + row * N + bn + tx * 8;
            float4 v0, v1;
            v0.x = __fadd_rn(accr[0], bb[0]); v0.y = __fadd_rn(accr[1], bb[1]);
            v0.z = __fadd_rn(accr[2], bb[2]); v0.w = __fadd_rn(accr[3], bb[3]);
            v1.x = __fadd_rn(accr[4], bb[4]); v1.y = __fadd_rn(accr[5], bb[5]);
            v1.z = __fadd_rn(accr[6], bb[6]); v1.w = __fadd_rn(accr[7], bb[7]);
            if (RELU) {
                v0.x = fmaxf(v0.x, 0.f); v0.y = fmaxf(v0.y, 0.f);
                v0.z = fmaxf(v0.z, 0.f); v0.w = fmaxf(v0.w, 0.f);
                v1.x = fmaxf(v1.x, 0.f); v1.y = fmaxf(v1.y, 0.f);
                v1.z = fmaxf(v1.z, 0.f); v1.w = fmaxf(v1.w, 0.f);
            }
            *(float4*)cp = v0;
            *(float4*)(cp + 4) = v1;
        }
    }
}

// ---------------------------------------------------------------------------
// VQ kernel: FROZEN numerics (verbatim from the passing round).
// ---------------------------------------------------------------------------
__global__ __launch_bounds__(256)
void vq_kernel(const float* __restrict__ Z, const float* __restrict__ emb,
               const float* __restrict__ Bk,
               float* __restrict__ zq, float* __restrict__ idx_out)
{
    __shared__ float z_s[32][DDIM];
    __shared__ float e_s[DDIM][128];
    __shared__ float bk_s[128];

    const int tid  = threadIdx.x;
    const int lane = tid & 31;
    const int warp = tid >> 5;
    const size_t row0 = (size_t)blockIdx.x * 32;
    const int r0 = warp * 4;

    {
        const float4* zg = (const float4*)(Z + row0 * DDIM);
        float4* zs = (float4*)z_s;
        zs[tid]       = zg[tid];
        zs[tid + 256] = zg[tid + 256];
    }
    __syncthreads();

    float Ar[4];
    #pragma unroll
    for (int rr = 0; rr < 4; rr++) {
        const float* zp = z_s[r0 + rr];
        float z0 = zp[lane], z1 = zp[lane + 32];
        float p = __fadd_rn(__fmul_rn(z0, z0), __fmul_rn(z1, z1));
        #pragma unroll
        for (int off = 16; off > 0; off >>= 1)
            p = __fadd_rn(p, __shfl_down_sync(0xffffffffu, p, off));
        Ar[rr] = __shfl_sync(0xffffffffu, p, 0);
    }

    float best_d[4];
    int   best_k[4];
    #pragma unroll
    for (int r = 0; r < 4; r++) { best_d[r] = 3.4e38f; best_k[r] = 0; }

    for (int c0 = 0; c0 < KCODES; c0 += 128) {
        __syncthreads();
        {
            int kk = tid >> 1;
            int d0 = (tid & 1) * 32;
            const float* ep = emb + (size_t)(c0 + kk) * DDIM + d0;
            #pragma unroll
            for (int i = 0; i < 32; i += 4) {
                float4 v = *(const float4*)(ep + i);
                e_s[d0 + i + 0][kk] = v.x;
                e_s[d0 + i + 1][kk] = v.y;
                e_s[d0 + i + 2][kk] = v.z;
                e_s[d0 + i + 3][kk] = v.w;
            }
            if (tid < 128) bk_s[tid] = Bk[c0 + tid];
        }
        __syncthreads();

        float accL[4][4], accH[4][4];
        #pragma unroll
        for (int r = 0; r < 4; r++)
            #pragma unroll
            for (int s = 0; s < 4; s++) { accL[r][s] = 0.f; accH[r][s] = 0.f; }

        #pragma unroll 8
        for (int d = 0; d < DDIM / 2; d++) {
            float zv[4], ev[4];
            #pragma unroll
            for (int r = 0; r < 4; r++) zv[r] = z_s[r0 + r][d];
            #pragma unroll
            for (int s = 0; s < 4; s++) ev[s] = e_s[d][s * 32 + lane];
            #pragma unroll
            for (int r = 0; r < 4; r++)
                #pragma unroll
                for (int s = 0; s < 4; s++)
                    accL[r][s] = fmaf(zv[r], ev[s], accL[r][s]);
        }
        #pragma unroll 8
        for (int d = DDIM / 2; d < DDIM; d++) {
            float zv[4], ev[4];
            #pragma unroll
            for (int r = 0; r < 4; r++) zv[r] = z_s[r0 + r][d];
            #pragma unroll
            for (int s = 0; s < 4; s++) ev[s] = e_s[d][s * 32 + lane];
            #pragma unroll
            for (int r = 0; r < 4; r++)
                #pragma unroll
                for (int s = 0; s < 4; s++)
                    accH[r][s] = fmaf(zv[r], ev[s], accH[r][s]);
        }

        #pragma unroll
        for (int r = 0; r < 4; r++) {
            #pragma unroll
            for (int s = 0; s < 4; s++) {
                int k = c0 + s * 32 + lane;
                float E  = __fadd_rn(accL[r][s], accH[r][s]);
                float t  = __fadd_rn(Ar[r], bk_s[s * 32 + lane]);
                float ds = __fadd_rn(t, -2.0f * E);
                if (ds < best_d[r]) { best_d[r] = ds; best_k[r] = k; }
            }
        }
    }

    #pragma unroll
    for (int r = 0; r < 4; r++) {
        float bd = best_d[r];
        int   bk = best_k[r];
        #pragma unroll
        for (int off = 16; off > 0; off >>= 1) {
            float od = __shfl_down_sync(0xffffffffu, bd, off);
            int   ok = __shfl_down_sync(0xffffffffu, bk, off);
            if (od < bd || (od == bd && ok < bk)) { bd = od; bk = ok; }
        }
        bk = __shfl_sync(0xffffffffu, bk, 0);

        size_t grow = row0 + (size_t)warp * 4 + r;
        zq[grow * DDIM + lane]      = emb[(size_t)bk * DDIM + lane];
        zq[grow * DDIM + 32 + lane] = emb[(size_t)bk * DDIM + 32 + lane];
        if (lane == 0) idx_out[grow] = (float)bk;
    }
}

// ---------------------------------------------------------------------------
extern "C" void kernel_launch(void* const* d_in, const int* in_sizes, int n_in,
                              void* d_out, int out_size)
{
    const float* x   = (const float*)d_in[0];
    const float* W1  = (const float*)d_in[1];
    const float* b1  = (const float*)d_in[2];
    const float* W2  = (const float*)d_in[3];
    const float* b2  = (const float*)d_in[4];
    const float* emb = (const float*)d_in[5];
    const float* W3  = (const float*)d_in[6];
    const float* b3  = (const float*)d_in[7];
    const float* W4  = (const float*)d_in[8];
    const float* b4  = (const float*)d_in[9];

    float* out     = (float*)d_out;
    float* x_recon = out;
    float* z       = out + (size_t)B_ * IN_DIM;
    float* zq      = z   + (size_t)B_ * (LLAT * DDIM);
    float* idxf    = zq  + (size_t)B_ * (LLAT * DDIM);

    float *h, *h2, *Bk;
    cudaGetSymbolAddress((void**)&h,  g_h);
    cudaGetSymbolAddress((void**)&h2, g_h2);
    cudaGetSymbolAddress((void**)&Bk, g_Bk);

    bk_kernel<<<(KCODES * 32 + 255) / 256, 256>>>(emb, Bk);

    sgemm<true ><<<dim3(HID    / 128, B_ / 128), 256>>>(x,  W1, b1, h,       B_, HID,    IN_DIM);
    sgemm<false><<<dim3(HID    / 128, B_ / 128), 256>>>(h,  W2, b2, z,       B_, HID,    HID);
    vq_kernel<<<(B_ * LLAT) / 32, 256>>>(z, emb, Bk, zq, idxf);
    sgemm<true ><<<dim3(HID    / 128, B_ / 128), 256>>>(zq, W3, b3, h2,      B_, HID,    HID);
    sgemm<false><<<dim3(IN_DIM / 128, B_ / 128), 256>>>(h2, W4, b4, x_recon, B_, IN_DIM, HID);
}

// round 7
// speedup vs baseline: 1.1768x; 1.0574x over previous
#include <cuda_runtime.h>
#include <cstddef>

// ---------------------------------------------------------------------------
// VQ-VAE forward. NUMERICS:
//  - Encoder GEMMs 1-2 + VQ: BIT-FROZEN (rel_err==0.0 contract; argmin must
//    never flip). FFMA2 per-element k-ascending fused FMA.
//  - Decoder: h2 = relu(sum_l T[l][k_l] + b3) via precomputed table
//    T[l][k][n] = sum_d emb[k][d]*W3[l*64+d][n]  (reassociation ~1e-7 rel,
//    budget 1e-3). GEMM4 stays FFMA2 exact-order (bit-irrelevant but cheap).
// ---------------------------------------------------------------------------

#define B_      8192
#define IN_DIM  1024
#define HID     2048
#define KCODES  512
#define DDIM    64
#define LLAT    32

typedef unsigned long long ull;

__device__ float g_h [(size_t)B_ * HID];
__device__ float g_h2[(size_t)B_ * HID];
__device__ float g_Bk[KCODES];
__device__ float g_T [(size_t)LLAT * KCODES * HID];   // 128 MB table

// packed f32x2 helpers (each lane independent IEEE rn fp32)
__device__ __forceinline__ ull pack_dup(unsigned u) {
    ull r;
    asm("mov.b64 %0, {%1, %1};" : "=l"(r) : "r"(u));
    return r;
}
__device__ __forceinline__ void ffma2(ull& acc, ull a, ull b) {
    asm("fma.rn.f32x2 %0, %1, %2, %0;" : "+l"(acc) : "l"(a), "l"(b));
}

// ---------------------------------------------------------------------------
__global__ void bk_kernel(const float* __restrict__ emb, float* __restrict__ Bk)
{
    int gwarp = (blockIdx.x * blockDim.x + threadIdx.x) >> 5;
    int lane  = threadIdx.x & 31;
    if (gwarp < KCODES) {
        const float* e = emb + (size_t)gwarp * DDIM;
        float e0 = e[2 * lane], e1 = e[2 * lane + 1];
        float p = __fadd_rn(__fmul_rn(e0, e0), __fmul_rn(e1, e1));
        #pragma unroll
        for (int off = 16; off > 0; off >>= 1)
            p = __fadd_rn(p, __shfl_down_sync(0xffffffffu, p, off));
        if (lane == 0) Bk[gwarp] = p;
    }
}

// ---------------------------------------------------------------------------
// Table build: T[l][k][n] = sum_d emb[k][d] * W3[l*64+d][n]
// grid (nt=16, kt=16, l=32), 256 threads. Tile: 32 k x 128 n, full d=64.
// ---------------------------------------------------------------------------
__global__ __launch_bounds__(256)
void build_T(const float* __restrict__ emb, const float* __restrict__ W3,
             float* __restrict__ T)
{
    __shared__ float e_s[32][DDIM];    // 8 KB   [k][d]
    __shared__ float w_s[DDIM][128];   // 32 KB  [d][n]

    const int tid = threadIdx.x;
    const int n0 = blockIdx.x * 128;
    const int k0 = blockIdx.y * 32;
    const int l  = blockIdx.z;

    // e_s: contiguous slab emb[k0*64 .. k0*64+2048)
    {
        const float4* src = (const float4*)(emb + (size_t)k0 * DDIM);
        float4* dst = (float4*)e_s;
        dst[tid]       = src[tid];
        dst[tid + 256] = src[tid + 256];
    }
    // w_s: 64 rows x 128 cols from W3 rows l*64+d
    {
        int d  = tid >> 2;            // 0..63
        int j0 = (tid & 3) * 32;      // 0,32,64,96
        const float* src = W3 + (size_t)(l * DDIM + d) * HID + n0 + j0;
        #pragma unroll
        for (int i = 0; i < 32; i += 4)
            *(float4*)&w_s[d][j0 + i] = *(const float4*)(src + i);
    }
    __syncthreads();

    const int kq  = tid >> 3;          // 0..31
    const int nq  = (tid & 7) * 16;    // 0..112

    float acc[16];
    #pragma unroll
    for (int i = 0; i < 16; i++) acc[i] = 0.f;

    #pragma unroll 16
    for (int d = 0; d < DDIM; d++) {
        float e = e_s[kq][d];
        #pragma unroll
        for (int i = 0; i < 16; i++)
            acc[i] = fmaf(e, w_s[d][nq + i], acc[i]);
    }

    float* tp = T + ((size_t)(l * KCODES + k0 + kq)) * HID + n0 + nq;
    #pragma unroll
    for (int i = 0; i < 16; i += 4)
        *(float4*)(tp + i) = *(const float4*)&acc[i];
}

// ---------------------------------------------------------------------------
// h2 = relu(sum_{l=0..31} T[l][k_l] + b3), one block per batch row.
// ---------------------------------------------------------------------------
__global__ __launch_bounds__(256)
void h2_kernel(const float* __restrict__ T, const float* __restrict__ idxf,
               const float* __restrict__ b3, float* __restrict__ h2)
{
    __shared__ int ks[LLAT];
    const int tid = threadIdx.x;
    const size_t b = blockIdx.x;

    if (tid < LLAT) ks[tid] = (int)idxf[b * LLAT + tid];
    __syncthreads();

    const int c0 = tid * 8;
    float acc[8];
    #pragma unroll
    for (int i = 0; i < 8; i++) acc[i] = 0.f;

    #pragma unroll 4
    for (int l = 0; l < LLAT; l++) {
        const float* tp = T + ((size_t)(l * KCODES + ks[l])) * HID + c0;
        float4 a = *(const float4*)tp;
        float4 c = *(const float4*)(tp + 4);
        acc[0] += a.x; acc[1] += a.y; acc[2] += a.z; acc[3] += a.w;
        acc[4] += c.x; acc[5] += c.y; acc[6] += c.z; acc[7] += c.w;
    }

    float4 bb0 = *(const float4*)(b3 + c0);
    float4 bb1 = *(const float4*)(b3 + c0 + 4);
    float4 v0, v1;
    v0.x = fmaxf(acc[0] + bb0.x, 0.f); v0.y = fmaxf(acc[1] + bb0.y, 0.f);
    v0.z = fmaxf(acc[2] + bb0.z, 0.f); v0.w = fmaxf(acc[3] + bb0.w, 0.f);
    v1.x = fmaxf(acc[4] + bb1.x, 0.f); v1.y = fmaxf(acc[5] + bb1.y, 0.f);
    v1.z = fmaxf(acc[6] + bb1.z, 0.f); v1.w = fmaxf(acc[7] + bb1.w, 0.f);

    float* hp = h2 + b * HID + c0;
    *(float4*)hp = v0;
    *(float4*)(hp + 4) = v1;
}

// ---------------------------------------------------------------------------
// SGEMM via FFMA2 (bit-exact per-element k-ascending FMA). FROZEN.
// ---------------------------------------------------------------------------
template<bool RELU>
__global__ __launch_bounds__(256, 2)
void sgemm(const float* __restrict__ A, const float* __restrict__ W,
           const float* __restrict__ bias, float* __restrict__ C,
           int M, int N, int K)
{
    __shared__ __align__(16) float As[2][8][128];
    __shared__ __align__(16) float Bs[2][8][128];

    const int tid = threadIdx.x;
    const int bm = blockIdx.y * 128;
    const int bn = blockIdx.x * 128;

    const int arow = tid >> 1;
    const int acol = (tid & 1) * 4;
    const int wrow = tid >> 5;
    const int wcol = (tid & 31) * 4;

    const int tx = tid & 15;
    const int ty = tid >> 4;

    ull acc2[4][8];
    #pragma unroll
    for (int i = 0; i < 4; i++)
        #pragma unroll
        for (int j = 0; j < 8; j++) acc2[i][j] = 0ull;

    const float* Aptr = A + (size_t)(bm + arow) * K + acol;
    const float* Wptr = W + (size_t)wrow * N + bn + wcol;

    const int nt = K >> 3;

    float4 av = *(const float4*)(Aptr);
    float4 wv = *(const float4*)(Wptr);
    As[0][acol + 0][arow] = av.x;
    As[0][acol + 1][arow] = av.y;
    As[0][acol + 2][arow] = av.z;
    As[0][acol + 3][arow] = av.w;
    *(float4*)&Bs[0][wrow][wcol] = wv;
    __syncthreads();

    for (int t = 0; t < nt; t++) {
        const int cur = t & 1;
        if (t + 1 < nt) {
            av = *(const float4*)(Aptr + (t + 1) * 8);
            wv = *(const float4*)(Wptr + (size_t)(t + 1) * 8 * N);
        }

        #pragma unroll
        for (int kk = 0; kk < 8; kk++) {
            ull a2[4];
            const ull* ap = (const ull*)&As[cur][kk][ty * 8];
            a2[0] = ap[0]; a2[1] = ap[1]; a2[2] = ap[2]; a2[3] = ap[3];

            uint4 bv0 = *(const uint4*)&Bs[cur][kk][tx * 8];
            uint4 bv1 = *(const uint4*)&Bs[cur][kk][tx * 8 + 4];
            ull bd[8];
            bd[0] = pack_dup(bv0.x); bd[1] = pack_dup(bv0.y);
            bd[2] = pack_dup(bv0.z); bd[3] = pack_dup(bv0.w);
            bd[4] = pack_dup(bv1.x); bd[5] = pack_dup(bv1.y);
            bd[6] = pack_dup(bv1.z); bd[7] = pack_dup(bv1.w);

            #pragma unroll
            for (int i = 0; i < 4; i++)
                #pragma unroll
                for (int j = 0; j < 8; j++)
                    ffma2(acc2[i][j], a2[i], bd[j]);
        }

        if (t + 1 < nt) {
            const int nxt = cur ^ 1;
            As[nxt][acol + 0][arow] = av.x;
            As[nxt][acol + 1][arow] = av.y;
            As[nxt][acol + 2][arow] = av.z;
            As[nxt][acol + 3][arow] = av.w;
            *(float4*)&Bs[nxt][wrow][wcol] = wv;
            __syncthreads();
        }
    }

    float bb[8];
    *(float4*)&bb[0] = *(const float4*)(bias + bn + tx * 8);
    *(float4*)&bb[4] = *(const float4*)(bias + bn + tx * 8 + 4);

    #pragma unroll
    for (int i2 = 0; i2 < 4; i2++) {
        float lo[8], hi[8];
        #pragma unroll
        for (int j = 0; j < 8; j++) {
            lo[j] = __uint_as_float((unsigned)(acc2[i2][j]));
            hi[j] = __uint_as_float((unsigned)(acc2[i2][j] >> 32));
        }
        #pragma unroll
        for (int half = 0; half < 2; half++) {
            const float* accr = half ? hi : lo;
            size_t row = (size_t)(bm + ty * 8 + i2 * 2 + half);
            float* cp = C + row * N + bn + tx * 8;
            float4 v0, v1;
            v0.x = __fadd_rn(accr[0], bb[0]); v0.y = __fadd_rn(accr[1], bb[1]);
            v0.z = __fadd_rn(accr[2], bb[2]); v0.w = __fadd_rn(accr[3], bb[3]);
            v1.x = __fadd_rn(accr[4], bb[4]); v1.y = __fadd_rn(accr[5], bb[5]);
            v1.z = __fadd_rn(accr[6], bb[6]); v1.w = __fadd_rn(accr[7], bb[7]);
            if (RELU) {
                v0.x = fmaxf(v0.x, 0.f); v0.y = fmaxf(v0.y, 0.f);
                v0.z = fmaxf(v0.z, 0.f); v0.w = fmaxf(v0.w, 0.f);
                v1.x = fmaxf(v1.x, 0.f); v1.y = fmaxf(v1.y, 0.f);
                v1.z = fmaxf(v1.z, 0.f); v1.w = fmaxf(v1.w, 0.f);
            }
            *(float4*)cp = v0;
            *(float4*)(cp + 4) = v1;
        }
    }
}

// ---------------------------------------------------------------------------
// VQ kernel: FROZEN numerics (verbatim from the passing round).
// ---------------------------------------------------------------------------
__global__ __launch_bounds__(256)
void vq_kernel(const float* __restrict__ Z, const float* __restrict__ emb,
               const float* __restrict__ Bk,
               float* __restrict__ zq, float* __restrict__ idx_out)
{
    __shared__ float z_s[32][DDIM];
    __shared__ float e_s[DDIM][128];
    __shared__ float bk_s[128];

    const int tid  = threadIdx.x;
    const int lane = tid & 31;
    const int warp = tid >> 5;
    const size_t row0 = (size_t)blockIdx.x * 32;
    const int r0 = warp * 4;

    {
        const float4* zg = (const float4*)(Z + row0 * DDIM);
        float4* zs = (float4*)z_s;
        zs[tid]       = zg[tid];
        zs[tid + 256] = zg[tid + 256];
    }
    __syncthreads();

    float Ar[4];
    #pragma unroll
    for (int rr = 0; rr < 4; rr++) {
        const float* zp = z_s[r0 + rr];
        float z0 = zp[lane], z1 = zp[lane + 32];
        float p = __fadd_rn(__fmul_rn(z0, z0), __fmul_rn(z1, z1));
        #pragma unroll
        for (int off = 16; off > 0; off >>= 1)
            p = __fadd_rn(p, __shfl_down_sync(0xffffffffu, p, off));
        Ar[rr] = __shfl_sync(0xffffffffu, p, 0);
    }

    float best_d[4];
    int   best_k[4];
    #pragma unroll
    for (int r = 0; r < 4; r++) { best_d[r] = 3.4e38f; best_k[r] = 0; }

    for (int c0 = 0; c0 < KCODES; c0 += 128) {
        __syncthreads();
        {
            int kk = tid >> 1;
            int d0 = (tid & 1) * 32;
            const float* ep = emb + (size_t)(c0 + kk) * DDIM + d0;
            #pragma unroll
            for (int i = 0; i < 32; i += 4) {
                float4 v = *(const float4*)(ep + i);
                e_s[d0 + i + 0][kk] = v.x;
                e_s[d0 + i + 1][kk] = v.y;
                e_s[d0 + i + 2][kk] = v.z;
                e_s[d0 + i + 3][kk] = v.w;
            }
            if (tid < 128) bk_s[tid] = Bk[c0 + tid];
        }
        __syncthreads();

        float accL[4][4], accH[4][4];
        #pragma unroll
        for (int r = 0; r < 4; r++)
            #pragma unroll
            for (int s = 0; s < 4; s++) { accL[r][s] = 0.f; accH[r][s] = 0.f; }

        #pragma unroll 8
        for (int d = 0; d < DDIM / 2; d++) {
            float zv[4], ev[4];
            #pragma unroll
            for (int r = 0; r < 4; r++) zv[r] = z_s[r0 + r][d];
            #pragma unroll
            for (int s = 0; s < 4; s++) ev[s] = e_s[d][s * 32 + lane];
            #pragma unroll
            for (int r = 0; r < 4; r++)
                #pragma unroll
                for (int s = 0; s < 4; s++)
                    accL[r][s] = fmaf(zv[r], ev[s], accL[r][s]);
        }
        #pragma unroll 8
        for (int d = DDIM / 2; d < DDIM; d++) {
            float zv[4], ev[4];
            #pragma unroll
            for (int r = 0; r < 4; r++) zv[r] = z_s[r0 + r][d];
            #pragma unroll
            for (int s = 0; s < 4; s++) ev[s] = e_s[d][s * 32 + lane];
            #pragma unroll
            for (int r = 0; r < 4; r++)
                #pragma unroll
                for (int s = 0; s < 4; s++)
                    accH[r][s] = fmaf(zv[r], ev[s], accH[r][s]);
        }

        #pragma unroll
        for (int r = 0; r < 4; r++) {
            #pragma unroll
            for (int s = 0; s < 4; s++) {
                int k = c0 + s * 32 + lane;
                float E  = __fadd_rn(accL[r][s], accH[r][s]);
                float t  = __fadd_rn(Ar[r], bk_s[s * 32 + lane]);
                float ds = __fadd_rn(t, -2.0f * E);
                if (ds < best_d[r]) { best_d[r] = ds; best_k[r] = k; }
            }
        }
    }

    #pragma unroll
    for (int r = 0; r < 4; r++) {
        float bd = best_d[r];
        int   bk = best_k[r];
        #pragma unroll
        for (int off = 16; off > 0; off >>= 1) {
            float od = __shfl_down_sync(0xffffffffu, bd, off);
            int   ok = __shfl_down_sync(0xffffffffu, bk, off);
            if (od < bd || (od == bd && ok < bk)) { bd = od; bk = ok; }
        }
        bk = __shfl_sync(0xffffffffu, bk, 0);

        size_t grow = row0 + (size_t)warp * 4 + r;
        zq[grow * DDIM + lane]      = emb[(size_t)bk * DDIM + lane];
        zq[grow * DDIM + 32 + lane] = emb[(size_t)bk * DDIM + 32 + lane];
        if (lane == 0) idx_out[grow] = (float)bk;
    }
}

// ---------------------------------------------------------------------------
extern "C" void kernel_launch(void* const* d_in, const int* in_sizes, int n_in,
                              void* d_out, int out_size)
{
    const float* x   = (const float*)d_in[0];
    const float* W1  = (const float*)d_in[1];
    const float* b1  = (const float*)d_in[2];
    const float* W2  = (const float*)d_in[3];
    const float* b2  = (const float*)d_in[4];
    const float* emb = (const float*)d_in[5];
    const float* W3  = (const float*)d_in[6];
    const float* b3  = (const float*)d_in[7];
    const float* W4  = (const float*)d_in[8];
    const float* b4  = (const float*)d_in[9];

    float* out     = (float*)d_out;
    float* x_recon = out;
    float* z       = out + (size_t)B_ * IN_DIM;
    float* zq      = z   + (size_t)B_ * (LLAT * DDIM);
    float* idxf    = zq  + (size_t)B_ * (LLAT * DDIM);

    float *h, *h2, *Bk, *T;
    cudaGetSymbolAddress((void**)&h,  g_h);
    cudaGetSymbolAddress((void**)&h2, g_h2);
    cudaGetSymbolAddress((void**)&Bk, g_Bk);
    cudaGetSymbolAddress((void**)&T,  g_T);

    bk_kernel<<<(KCODES * 32 + 255) / 256, 256>>>(emb, Bk);
    // decoder table (independent of x; overlaps with encoder GEMMs)
    build_T<<<dim3(HID / 128, KCODES / 32, LLAT), 256>>>(emb, W3, T);

    sgemm<true ><<<dim3(HID    / 128, B_ / 128), 256>>>(x,  W1, b1, h, B_, HID, IN_DIM);
    sgemm<false><<<dim3(HID    / 128, B_ / 128), 256>>>(h,  W2, b2, z, B_, HID, HID);
    vq_kernel<<<(B_ * LLAT) / 32, 256>>>(z, emb, Bk, zq, idxf);
    // h2 = relu(sum_l T[l][k_l] + b3)
    h2_kernel<<<B_, 256>>>(T, idxf, b3, h2);
    sgemm<false><<<dim3(IN_DIM / 128, B_ / 128), 256>>>(h2, W4, b4, x_recon, B_, IN_DIM, HID);
}

// round 8
// speedup vs baseline: 1.2210x; 1.0376x over previous
#include <cuda_runtime.h>
#include <cstddef>

// ---------------------------------------------------------------------------
// VQ-VAE forward. NUMERICS:
//  - Encoder GEMMs 1-2 + VQ: BIT-FROZEN (argmin must never flip).
//    VQ this round: same per-element arithmetic (A tree, half-split E,
//    ascending-d fused FMA, dist formula, first-index tie-break) but packed
//    two codes per lane via fma.rn.f32x2 (each half independent IEEE rn).
//  - Decoder (build_T / h2 / GEMM4): reassociation allowed (budget 1e-3,
//    currently ~1e-6). This round: coalesced W3 loads, higher-MLP h2.
// ---------------------------------------------------------------------------

#define B_      8192
#define IN_DIM  1024
#define HID     2048
#define KCODES  512
#define DDIM    64
#define LLAT    32

typedef unsigned long long ull;

__device__ float g_h [(size_t)B_ * HID];
__device__ float g_h2[(size_t)B_ * HID];
__device__ float g_Bk[KCODES];
__device__ float g_T [(size_t)LLAT * KCODES * HID];   // 128 MB table

// packed f32x2 helpers (each lane independent IEEE rn fp32)
__device__ __forceinline__ ull pack_dup(unsigned u) {
    ull r;
    asm("mov.b64 %0, {%1, %1};" : "=l"(r) : "r"(u));
    return r;
}
__device__ __forceinline__ void ffma2(ull& acc, ull a, ull b) {
    asm("fma.rn.f32x2 %0, %1, %2, %0;" : "+l"(acc) : "l"(a), "l"(b));
}

// ---------------------------------------------------------------------------
__global__ void bk_kernel(const float* __restrict__ emb, float* __restrict__ Bk)
{
    int gwarp = (blockIdx.x * blockDim.x + threadIdx.x) >> 5;
    int lane  = threadIdx.x & 31;
    if (gwarp < KCODES) {
        const float* e = emb + (size_t)gwarp * DDIM;
        float e0 = e[2 * lane], e1 = e[2 * lane + 1];
        float p = __fadd_rn(__fmul_rn(e0, e0), __fmul_rn(e1, e1));
        #pragma unroll
        for (int off = 16; off > 0; off >>= 1)
            p = __fadd_rn(p, __shfl_down_sync(0xffffffffu, p, off));
        if (lane == 0) Bk[gwarp] = p;
    }
}

// ---------------------------------------------------------------------------
// Table build: T[l][k][n] = sum_d emb[k][d] * W3[l*64+d][n]
// grid (16,16,32), 256 threads. Coalesced W3 tile load.
// ---------------------------------------------------------------------------
__global__ __launch_bounds__(256)
void build_T(const float* __restrict__ emb, const float* __restrict__ W3,
             float* __restrict__ T)
{
    __shared__ float e_s[32][DDIM];    // [k][d]
    __shared__ float w_s[DDIM][128];   // [d][n]

    const int tid = threadIdx.x;
    const int n0 = blockIdx.x * 128;
    const int k0 = blockIdx.y * 32;
    const int l  = blockIdx.z;

    {
        const float4* src = (const float4*)(emb + (size_t)k0 * DDIM);
        float4* dst = (float4*)e_s;
        dst[tid]       = src[tid];
        dst[tid + 256] = src[tid + 256];
    }
    // coalesced: warp reads one 512B row-segment per step
    {
        #pragma unroll
        for (int i = 0; i < 8; i++) {
            int f   = i * 256 + tid;       // float4 index within 64x128 tile
            int row = f >> 5;              // 0..63
            int c4  = (f & 31) * 4;        // 0..124
            *(float4*)&w_s[row][c4] =
                *(const float4*)(W3 + (size_t)(l * DDIM + row) * HID + n0 + c4);
        }
    }
    __syncthreads();

    const int kq = tid >> 3;           // 0..31
    const int nq = (tid & 7) * 16;     // 0..112

    float acc[16];
    #pragma unroll
    for (int i = 0; i < 16; i++) acc[i] = 0.f;

    #pragma unroll 16
    for (int d = 0; d < DDIM; d++) {
        float e = e_s[kq][d];
        #pragma unroll
        for (int i4 = 0; i4 < 16; i4 += 4) {
            float4 w = *(const float4*)&w_s[d][nq + i4];
            acc[i4 + 0] = fmaf(e, w.x, acc[i4 + 0]);
            acc[i4 + 1] = fmaf(e, w.y, acc[i4 + 1]);
            acc[i4 + 2] = fmaf(e, w.z, acc[i4 + 2]);
            acc[i4 + 3] = fmaf(e, w.w, acc[i4 + 3]);
        }
    }

    float* tp = T + ((size_t)(l * KCODES + k0 + kq)) * HID + n0 + nq;
    #pragma unroll
    for (int i = 0; i < 16; i += 4)
        *(float4*)(tp + i) = *(const float4*)&acc[i];
}

// ---------------------------------------------------------------------------
// h2 = relu(sum_l T[l][k_l] + b3). 512 threads, one batch row per block,
// float4 per thread, two accumulation banks for MLP.
// ---------------------------------------------------------------------------
__global__ __launch_bounds__(512)
void h2_kernel(const float* __restrict__ T, const float* __restrict__ idxf,
               const float* __restrict__ b3, float* __restrict__ h2)
{
    __shared__ int ks[LLAT];
    const int tid = threadIdx.x;
    const size_t b = blockIdx.x;

    if (tid < LLAT) ks[tid] = (int)idxf[b * LLAT + tid];
    __syncthreads();

    const int c0 = tid * 4;
    float a0 = 0.f, a1 = 0.f, a2 = 0.f, a3 = 0.f;
    float c0f = 0.f, c1f = 0.f, c2f = 0.f, c3f = 0.f;

    #pragma unroll 8
    for (int l = 0; l < LLAT; l += 2) {
        float4 u = *(const float4*)(T + ((size_t)(l * KCODES + ks[l])) * HID + c0);
        float4 v = *(const float4*)(T + ((size_t)((l + 1) * KCODES + ks[l + 1])) * HID + c0);
        a0 += u.x; a1 += u.y; a2 += u.z; a3 += u.w;
        c0f += v.x; c1f += v.y; c2f += v.z; c3f += v.w;
    }

    float4 bb = *(const float4*)(b3 + c0);
    float4 o;
    o.x = fmaxf(a0 + c0f + bb.x, 0.f);
    o.y = fmaxf(a1 + c1f + bb.y, 0.f);
    o.z = fmaxf(a2 + c2f + bb.z, 0.f);
    o.w = fmaxf(a3 + c3f + bb.w, 0.f);

    *(float4*)(h2 + b * HID + c0) = o;
}

// ---------------------------------------------------------------------------
// SGEMM via FFMA2 (bit-exact per-element k-ascending FMA). FROZEN.
// ---------------------------------------------------------------------------
template<bool RELU>
__global__ __launch_bounds__(256, 2)
void sgemm(const float* __restrict__ A, const float* __restrict__ W,
           const float* __restrict__ bias, float* __restrict__ C,
           int M, int N, int K)
{
    __shared__ __align__(16) float As[2][8][128];
    __shared__ __align__(16) float Bs[2][8][128];

    const int tid = threadIdx.x;
    const int bm = blockIdx.y * 128;
    const int bn = blockIdx.x * 128;

    const int arow = tid >> 1;
    const int acol = (tid & 1) * 4;
    const int wrow = tid >> 5;
    const int wcol = (tid & 31) * 4;

    const int tx = tid & 15;
    const int ty = tid >> 4;

    ull acc2[4][8];
    #pragma unroll
    for (int i = 0; i < 4; i++)
        #pragma unroll
        for (int j = 0; j < 8; j++) acc2[i][j] = 0ull;

    const float* Aptr = A + (size_t)(bm + arow) * K + acol;
    const float* Wptr = W + (size_t)wrow * N + bn + wcol;

    const int nt = K >> 3;

    float4 av = *(const float4*)(Aptr);
    float4 wv = *(const float4*)(Wptr);
    As[0][acol + 0][arow] = av.x;
    As[0][acol + 1][arow] = av.y;
    As[0][acol + 2][arow] = av.z;
    As[0][acol + 3][arow] = av.w;
    *(float4*)&Bs[0][wrow][wcol] = wv;
    __syncthreads();

    for (int t = 0; t < nt; t++) {
        const int cur = t & 1;
        if (t + 1 < nt) {
            av = *(const float4*)(Aptr + (t + 1) * 8);
            wv = *(const float4*)(Wptr + (size_t)(t + 1) * 8 * N);
        }

        #pragma unroll
        for (int kk = 0; kk < 8; kk++) {
            ull a2[4];
            const ull* ap = (const ull*)&As[cur][kk][ty * 8];
            a2[0] = ap[0]; a2[1] = ap[1]; a2[2] = ap[2]; a2[3] = ap[3];

            uint4 bv0 = *(const uint4*)&Bs[cur][kk][tx * 8];
            uint4 bv1 = *(const uint4*)&Bs[cur][kk][tx * 8 + 4];
            ull bd[8];
            bd[0] = pack_dup(bv0.x); bd[1] = pack_dup(bv0.y);
            bd[2] = pack_dup(bv0.z); bd[3] = pack_dup(bv0.w);
            bd[4] = pack_dup(bv1.x); bd[5] = pack_dup(bv1.y);
            bd[6] = pack_dup(bv1.z); bd[7] = pack_dup(bv1.w);

            #pragma unroll
            for (int i = 0; i < 4; i++)
                #pragma unroll
                for (int j = 0; j < 8; j++)
                    ffma2(acc2[i][j], a2[i], bd[j]);
        }

        if (t + 1 < nt) {
            const int nxt = cur ^ 1;
            As[nxt][acol + 0][arow] = av.x;
            As[nxt][acol + 1][arow] = av.y;
            As[nxt][acol + 2][arow] = av.z;
            As[nxt][acol + 3][arow] = av.w;
            *(float4*)&Bs[nxt][wrow][wcol] = wv;
            __syncthreads();
        }
    }

    float bb[8];
    *(float4*)&bb[0] = *(const float4*)(bias + bn + tx * 8);
    *(float4*)&bb[4] = *(const float4*)(bias + bn + tx * 8 + 4);

    #pragma unroll
    for (int i2 = 0; i2 < 4; i2++) {
        float lo[8], hi[8];
        #pragma unroll
        for (int j = 0; j < 8; j++) {
            lo[j] = __uint_as_float((unsigned)(acc2[i2][j]));
            hi[j] = __uint_as_float((unsigned)(acc2[i2][j] >> 32));
        }
        #pragma unroll
        for (int half = 0; half < 2; half++) {
            const float* accr = half ? hi : lo;
            size_t row = (size_t)(bm + ty * 8 + i2 * 2 + half);
            float* cp = C + row * N + bn + tx * 8;
            float4 v0, v1;
            v0.x = __fadd_rn(accr[0], bb[0]); v0.y = __fadd_rn(accr[1], bb[1]);
            v0.z = __fadd_rn(accr[2], bb[2]); v0.w = __fadd_rn(accr[3], bb[3]);
            v1.x = __fadd_rn(accr[4], bb[4]); v1.y = __fadd_rn(accr[5], bb[5]);
            v1.z = __fadd_rn(accr[6], bb[6]); v1.w = __fadd_rn(accr[7], bb[7]);
            if (RELU) {
                v0.x = fmaxf(v0.x, 0.f); v0.y = fmaxf(v0.y, 0.f);
                v0.z = fmaxf(v0.z, 0.f); v0.w = fmaxf(v0.w, 0.f);
                v1.x = fmaxf(v1.x, 0.f); v1.y = fmaxf(v1.y, 0.f);
                v1.z = fmaxf(v1.z, 0.f); v1.w = fmaxf(v1.w, 0.f);
            }
            *(float4*)cp = v0;
            *(float4*)(cp + 4) = v1;
        }
    }
}

// ---------------------------------------------------------------------------
// VQ kernel: FROZEN per-element numerics, FFMA2-packed (2 codes per lane).
// Lane l handles k = c0 + s*64 + 2*l + j (s in {0,1}, j in {0,1}); each
// packed half accumulates its own code in ascending d: identical sequence
// fl ops as the scalar version. Global argmin + first-index tie-break
// unchanged (per-lane scan ascending k, warp reduce with k tie-break).
// ---------------------------------------------------------------------------
__global__ __launch_bounds__(256)
void vq_kernel(const float* __restrict__ Z, const float* __restrict__ emb,
               const float* __restrict__ Bk,
               float* __restrict__ zq, float* __restrict__ idx_out)
{
    __shared__ float z_s[32][DDIM];
    __shared__ __align__(16) float e_s[DDIM][128];
    __shared__ float bk_s[128];

    const int tid  = threadIdx.x;
    const int lane = tid & 31;
    const int warp = tid >> 5;
    const size_t row0 = (size_t)blockIdx.x * 32;
    const int r0 = warp * 4;

    {
        const float4* zg = (const float4*)(Z + row0 * DDIM);
        float4* zs = (float4*)z_s;
        zs[tid]       = zg[tid];
        zs[tid + 256] = zg[tid + 256];
    }
    __syncthreads();

    // A per row: strided-pair warp tree (FROZEN)
    float Ar[4];
    #pragma unroll
    for (int rr = 0; rr < 4; rr++) {
        const float* zp = z_s[r0 + rr];
        float z0 = zp[lane], z1 = zp[lane + 32];
        float p = __fadd_rn(__fmul_rn(z0, z0), __fmul_rn(z1, z1));
        #pragma unroll
        for (int off = 16; off > 0; off >>= 1)
            p = __fadd_rn(p, __shfl_down_sync(0xffffffffu, p, off));
        Ar[rr] = __shfl_sync(0xffffffffu, p, 0);
    }

    float best_d[4];
    int   best_k[4];
    #pragma unroll
    for (int r = 0; r < 4; r++) { best_d[r] = 3.4e38f; best_k[r] = 0; }

    for (int c0 = 0; c0 < KCODES; c0 += 128) {
        __syncthreads();
        {
            int kk = tid >> 1;
            int d0 = (tid & 1) * 32;
            const float* ep = emb + (size_t)(c0 + kk) * DDIM + d0;
            #pragma unroll
            for (int i = 0; i < 32; i += 4) {
                float4 v = *(const float4*)(ep + i);
                e_s[d0 + i + 0][kk] = v.x;
                e_s[d0 + i + 1][kk] = v.y;
                e_s[d0 + i + 2][kk] = v.z;
                e_s[d0 + i + 3][kk] = v.w;
            }
            if (tid < 128) bk_s[tid] = Bk[c0 + tid];
        }
        __syncthreads();

        // packed accumulators: [row r][group s], halves = codes 2lane / 2lane+1
        ull accL[4][2], accH[4][2];
        #pragma unroll
        for (int r = 0; r < 4; r++)
            #pragma unroll
            for (int s = 0; s < 2; s++) { accL[r][s] = 0ull; accH[r][s] = 0ull; }

        // low half d = 0..31 (FROZEN: ascending d, fused FMA per element)
        #pragma unroll
        for (int d4 = 0; d4 < DDIM / 2; d4 += 4) {
            float4 zr[4];
            #pragma unroll
            for (int r = 0; r < 4; r++)
                zr[r] = *(const float4*)&z_s[r0 + r][d4];
            #pragma unroll
            for (int dd = 0; dd < 4; dd++) {
                int d = d4 + dd;
                ull ev0 = *(const ull*)&e_s[d][2 * lane];
                ull ev1 = *(const ull*)&e_s[d][64 + 2 * lane];
                #pragma unroll
                for (int r = 0; r < 4; r++) {
                    float zf = (dd == 0) ? zr[r].x : (dd == 1) ? zr[r].y
                             : (dd == 2) ? zr[r].z : zr[r].w;
                    ull zd = pack_dup(__float_as_uint(zf));
                    ffma2(accL[r][0], zd, ev0);
                    ffma2(accL[r][1], zd, ev1);
                }
            }
        }
        // high half d = 32..63
        #pragma unroll
        for (int d4 = DDIM / 2; d4 < DDIM; d4 += 4) {
            float4 zr[4];
            #pragma unroll
            for (int r = 0; r < 4; r++)
                zr[r] = *(const float4*)&z_s[r0 + r][d4];
            #pragma unroll
            for (int dd = 0; dd < 4; dd++) {
                int d = d4 + dd;
                ull ev0 = *(const ull*)&e_s[d][2 * lane];
                ull ev1 = *(const ull*)&e_s[d][64 + 2 * lane];
                #pragma unroll
                for (int r = 0; r < 4; r++) {
                    float zf = (dd == 0) ? zr[r].x : (dd == 1) ? zr[r].y
                             : (dd == 2) ? zr[r].z : zr[r].w;
                    ull zd = pack_dup(__float_as_uint(zf));
                    ffma2(accH[r][0], zd, ev0);
                    ffma2(accH[r][1], zd, ev1);
                }
            }
        }

        // dist + per-lane best, k ascending (s asc, j asc)  (FROZEN semantics)
        #pragma unroll
        for (int r = 0; r < 4; r++) {
            #pragma unroll
            for (int s = 0; s < 2; s++) {
                #pragma unroll
                for (int j = 0; j < 2; j++) {
                    float eL = __uint_as_float(j == 0 ? (unsigned)accL[r][s]
                                                      : (unsigned)(accL[r][s] >> 32));
                    float eH = __uint_as_float(j == 0 ? (unsigned)accH[r][s]
                                                      : (unsigned)(accH[r][s] >> 32));
                    int kc = s * 64 + 2 * lane + j;
                    float E  = __fadd_rn(eL, eH);
                    float t  = __fadd_rn(Ar[r], bk_s[kc]);
                    float ds = __fadd_rn(t, -2.0f * E);
                    int k = c0 + kc;
                    if (ds < best_d[r]) { best_d[r] = ds; best_k[r] = k; }
                }
            }
        }
    }

    #pragma unroll
    for (int r = 0; r < 4; r++) {
        float bd = best_d[r];
        int   bk = best_k[r];
        #pragma unroll
        for (int off = 16; off > 0; off >>= 1) {
            float od = __shfl_down_sync(0xffffffffu, bd, off);
            int   ok = __shfl_down_sync(0xffffffffu, bk, off);
            if (od < bd || (od == bd && ok < bk)) { bd = od; bk = ok; }
        }
        bk = __shfl_sync(0xffffffffu, bk, 0);

        size_t grow = row0 + (size_t)warp * 4 + r;
        zq[grow * DDIM + lane]      = emb[(size_t)bk * DDIM + lane];
        zq[grow * DDIM + 32 + lane] = emb[(size_t)bk * DDIM + 32 + lane];
        if (lane == 0) idx_out[grow] = (float)bk;
    }
}

// ---------------------------------------------------------------------------
extern "C" void kernel_launch(void* const* d_in, const int* in_sizes, int n_in,
                              void* d_out, int out_size)
{
    const float* x   = (const float*)d_in[0];
    const float* W1  = (const float*)d_in[1];
    const float* b1  = (const float*)d_in[2];
    const float* W2  = (const float*)d_in[3];
    const float* b2  = (const float*)d_in[4];
    const float* emb = (const float*)d_in[5];
    const float* W3  = (const float*)d_in[6];
    const float* b3  = (const float*)d_in[7];
    const float* W4  = (const float*)d_in[8];
    const float* b4  = (const float*)d_in[9];

    float* out     = (float*)d_out;
    float* x_recon = out;
    float* z       = out + (size_t)B_ * IN_DIM;
    float* zq      = z   + (size_t)B_ * (LLAT * DDIM);
    float* idxf    = zq  + (size_t)B_ * (LLAT * DDIM);

    float *h, *h2, *Bk, *T;
    cudaGetSymbolAddress((void**)&h,  g_h);
    cudaGetSymbolAddress((void**)&h2, g_h2);
    cudaGetSymbolAddress((void**)&Bk, g_Bk);
    cudaGetSymbolAddress((void**)&T,  g_T);

    bk_kernel<<<(KCODES * 32 + 255) / 256, 256>>>(emb, Bk);
    build_T<<<dim3(HID / 128, KCODES / 32, LLAT), 256>>>(emb, W3, T);

    sgemm<true ><<<dim3(HID    / 128, B_ / 128), 256>>>(x,  W1, b1, h, B_, HID, IN_DIM);
    sgemm<false><<<dim3(HID    / 128, B_ / 128), 256>>>(h,  W2, b2, z, B_, HID, HID);
    vq_kernel<<<(B_ * LLAT) / 32, 256>>>(z, emb, Bk, zq, idxf);
    h2_kernel<<<B_, 512>>>(T, idxf, b3, h2);
    sgemm<false><<<dim3(IN_DIM / 128, B_ / 128), 256>>>(h2, W4, b4, x_recon, B_, IN_DIM, HID);
}

// round 9
// speedup vs baseline: 1.2280x; 1.0057x over previous
#include <cuda_runtime.h>
#include <cstddef>

// ---------------------------------------------------------------------------
// VQ-VAE forward. NUMERICS:
//  - Encoder GEMMs 1-2 + VQ: BIT-FROZEN (argmin must never flip).
//  - Decoder (build_T / h2 / GEMM4): reassociation allowed (budget 1e-3,
//    currently ~1e-6). This round: L2-slab-aware h2 gather tiling.
// ---------------------------------------------------------------------------

#define B_      8192
#define IN_DIM  1024
#define HID     2048
#define KCODES  512
#define DDIM    64
#define LLAT    32

typedef unsigned long long ull;

__device__ float g_h [(size_t)B_ * HID];
__device__ float g_h2[(size_t)B_ * HID];
__device__ float g_Bk[KCODES];
__device__ float g_T [(size_t)LLAT * KCODES * HID];   // 128 MB table

// packed f32x2 helpers (each lane independent IEEE rn fp32)
__device__ __forceinline__ ull pack_dup(unsigned u) {
    ull r;
    asm("mov.b64 %0, {%1, %1};" : "=l"(r) : "r"(u));
    return r;
}
__device__ __forceinline__ void ffma2(ull& acc, ull a, ull b) {
    asm("fma.rn.f32x2 %0, %1, %2, %0;" : "+l"(acc) : "l"(a), "l"(b));
}

// ---------------------------------------------------------------------------
__global__ void bk_kernel(const float* __restrict__ emb, float* __restrict__ Bk)
{
    int gwarp = (blockIdx.x * blockDim.x + threadIdx.x) >> 5;
    int lane  = threadIdx.x & 31;
    if (gwarp < KCODES) {
        const float* e = emb + (size_t)gwarp * DDIM;
        float e0 = e[2 * lane], e1 = e[2 * lane + 1];
        float p = __fadd_rn(__fmul_rn(e0, e0), __fmul_rn(e1, e1));
        #pragma unroll
        for (int off = 16; off > 0; off >>= 1)
            p = __fadd_rn(p, __shfl_down_sync(0xffffffffu, p, off));
        if (lane == 0) Bk[gwarp] = p;
    }
}

// ---------------------------------------------------------------------------
// Table build: T[l][k][n] = sum_d emb[k][d] * W3[l*64+d][n]
// ---------------------------------------------------------------------------
__global__ __launch_bounds__(256)
void build_T(const float* __restrict__ emb, const float* __restrict__ W3,
             float* __restrict__ T)
{
    __shared__ float e_s[32][DDIM];    // [k][d]
    __shared__ float w_s[DDIM][128];   // [d][n]

    const int tid = threadIdx.x;
    const int n0 = blockIdx.x * 128;
    const int k0 = blockIdx.y * 32;
    const int l  = blockIdx.z;

    {
        const float4* src = (const float4*)(emb + (size_t)k0 * DDIM);
        float4* dst = (float4*)e_s;
        dst[tid]       = src[tid];
        dst[tid + 256] = src[tid + 256];
    }
    {
        #pragma unroll
        for (int i = 0; i < 8; i++) {
            int f   = i * 256 + tid;
            int row = f >> 5;
            int c4  = (f & 31) * 4;
            *(float4*)&w_s[row][c4] =
                *(const float4*)(W3 + (size_t)(l * DDIM + row) * HID + n0 + c4);
        }
    }
    __syncthreads();

    const int kq = tid >> 3;
    const int nq = (tid & 7) * 16;

    float acc[16];
    #pragma unroll
    for (int i = 0; i < 16; i++) acc[i] = 0.f;

    #pragma unroll 16
    for (int d = 0; d < DDIM; d++) {
        float e = e_s[kq][d];
        #pragma unroll
        for (int i4 = 0; i4 < 16; i4 += 4) {
            float4 w = *(const float4*)&w_s[d][nq + i4];
            acc[i4 + 0] = fmaf(e, w.x, acc[i4 + 0]);
            acc[i4 + 1] = fmaf(e, w.y, acc[i4 + 1]);
            acc[i4 + 2] = fmaf(e, w.z, acc[i4 + 2]);
            acc[i4 + 3] = fmaf(e, w.w, acc[i4 + 3]);
        }
    }

    float* tp = T + ((size_t)(l * KCODES + k0 + kq)) * HID + n0 + nq;
    #pragma unroll
    for (int i = 0; i < 16; i += 4)
        *(float4*)(tp + i) = *(const float4*)&acc[i];
}

// ---------------------------------------------------------------------------
// h2 = relu(sum_l T[l][k_l] + b3).
// Grid (B/32 fast, HID/128 slow) -> concurrent CTAs share one 8MB column
// slab of T (L2-resident). Block 256 thr: thread = (col-quad, 4-row group).
// ---------------------------------------------------------------------------
__global__ __launch_bounds__(256)
void h2_kernel(const float* __restrict__ T, const float* __restrict__ idxf,
               const float* __restrict__ b3, float* __restrict__ h2)
{
    __shared__ int ks[32][LLAT];       // [row][l]

    const int tid = threadIdx.x;
    const int b0  = blockIdx.x * 32;   // batch rows
    const int c0  = blockIdx.y * 128;  // hid cols

    #pragma unroll
    for (int i = tid; i < 32 * LLAT; i += 256)
        ks[i >> 5][i & 31] = (int)__ldg(&idxf[(size_t)(b0 + (i >> 5)) * LLAT + (i & 31)]);
    __syncthreads();

    const int cq = c0 + (tid & 31) * 4;   // column (float4)
    const int r0 = (tid >> 5) * 4;        // first of 4 rows

    float4 a0 = {0,0,0,0}, a1 = {0,0,0,0}, a2 = {0,0,0,0}, a3 = {0,0,0,0};

    #pragma unroll 4
    for (int l = 0; l < LLAT; l++) {
        const size_t base = (size_t)l * KCODES;
        float4 v0 = *(const float4*)(T + (base + ks[r0 + 0][l]) * HID + cq);
        float4 v1 = *(const float4*)(T + (base + ks[r0 + 1][l]) * HID + cq);
        float4 v2 = *(const float4*)(T + (base + ks[r0 + 2][l]) * HID + cq);
        float4 v3 = *(const float4*)(T + (base + ks[r0 + 3][l]) * HID + cq);
        a0.x += v0.x; a0.y += v0.y; a0.z += v0.z; a0.w += v0.w;
        a1.x += v1.x; a1.y += v1.y; a1.z += v1.z; a1.w += v1.w;
        a2.x += v2.x; a2.y += v2.y; a2.z += v2.z; a2.w += v2.w;
        a3.x += v3.x; a3.y += v3.y; a3.z += v3.z; a3.w += v3.w;
    }

    float4 bb = *(const float4*)(b3 + cq);
    float4 o0, o1, o2, o3;
    o0.x = fmaxf(a0.x + bb.x, 0.f); o0.y = fmaxf(a0.y + bb.y, 0.f);
    o0.z = fmaxf(a0.z + bb.z, 0.f); o0.w = fmaxf(a0.w + bb.w, 0.f);
    o1.x = fmaxf(a1.x + bb.x, 0.f); o1.y = fmaxf(a1.y + bb.y, 0.f);
    o1.z = fmaxf(a1.z + bb.z, 0.f); o1.w = fmaxf(a1.w + bb.w, 0.f);
    o2.x = fmaxf(a2.x + bb.x, 0.f); o2.y = fmaxf(a2.y + bb.y, 0.f);
    o2.z = fmaxf(a2.z + bb.z, 0.f); o2.w = fmaxf(a2.w + bb.w, 0.f);
    o3.x = fmaxf(a3.x + bb.x, 0.f); o3.y = fmaxf(a3.y + bb.y, 0.f);
    o3.z = fmaxf(a3.z + bb.z, 0.f); o3.w = fmaxf(a3.w + bb.w, 0.f);

    *(float4*)(h2 + (size_t)(b0 + r0 + 0) * HID + cq) = o0;
    *(float4*)(h2 + (size_t)(b0 + r0 + 1) * HID + cq) = o1;
    *(float4*)(h2 + (size_t)(b0 + r0 + 2) * HID + cq) = o2;
    *(float4*)(h2 + (size_t)(b0 + r0 + 3) * HID + cq) = o3;
}

// ---------------------------------------------------------------------------
// SGEMM via FFMA2 (bit-exact per-element k-ascending FMA). FROZEN.
// ---------------------------------------------------------------------------
template<bool RELU>
__global__ __launch_bounds__(256, 2)
void sgemm(const float* __restrict__ A, const float* __restrict__ W,
           const float* __restrict__ bias, float* __restrict__ C,
           int M, int N, int K)
{
    __shared__ __align__(16) float As[2][8][128];
    __shared__ __align__(16) float Bs[2][8][128];

    const int tid = threadIdx.x;
    const int bm = blockIdx.y * 128;
    const int bn = blockIdx.x * 128;

    const int arow = tid >> 1;
    const int acol = (tid & 1) * 4;
    const int wrow = tid >> 5;
    const int wcol = (tid & 31) * 4;

    const int tx = tid & 15;
    const int ty = tid >> 4;

    ull acc2[4][8];
    #pragma unroll
    for (int i = 0; i < 4; i++)
        #pragma unroll
        for (int j = 0; j < 8; j++) acc2[i][j] = 0ull;

    const float* Aptr = A + (size_t)(bm + arow) * K + acol;
    const float* Wptr = W + (size_t)wrow * N + bn + wcol;

    const int nt = K >> 3;

    float4 av = *(const float4*)(Aptr);
    float4 wv = *(const float4*)(Wptr);
    As[0][acol + 0][arow] = av.x;
    As[0][acol + 1][arow] = av.y;
    As[0][acol + 2][arow] = av.z;
    As[0][acol + 3][arow] = av.w;
    *(float4*)&Bs[0][wrow][wcol] = wv;
    __syncthreads();

    for (int t = 0; t < nt; t++) {
        const int cur = t & 1;
        if (t + 1 < nt) {
            av = *(const float4*)(Aptr + (t + 1) * 8);
            wv = *(const float4*)(Wptr + (size_t)(t + 1) * 8 * N);
        }

        #pragma unroll
        for (int kk = 0; kk < 8; kk++) {
            ull a2[4];
            const ull* ap = (const ull*)&As[cur][kk][ty * 8];
            a2[0] = ap[0]; a2[1] = ap[1]; a2[2] = ap[2]; a2[3] = ap[3];

            uint4 bv0 = *(const uint4*)&Bs[cur][kk][tx * 8];
            uint4 bv1 = *(const uint4*)&Bs[cur][kk][tx * 8 + 4];
            ull bd[8];
            bd[0] = pack_dup(bv0.x); bd[1] = pack_dup(bv0.y);
            bd[2] = pack_dup(bv0.z); bd[3] = pack_dup(bv0.w);
            bd[4] = pack_dup(bv1.x); bd[5] = pack_dup(bv1.y);
            bd[6] = pack_dup(bv1.z); bd[7] = pack_dup(bv1.w);

            #pragma unroll
            for (int i = 0; i < 4; i++)
                #pragma unroll
                for (int j = 0; j < 8; j++)
                    ffma2(acc2[i][j], a2[i], bd[j]);
        }

        if (t + 1 < nt) {
            const int nxt = cur ^ 1;
            As[nxt][acol + 0][arow] = av.x;
            As[nxt][acol + 1][arow] = av.y;
            As[nxt][acol + 2][arow] = av.z;
            As[nxt][acol + 3][arow] = av.w;
            *(float4*)&Bs[nxt][wrow][wcol] = wv;
            __syncthreads();
        }
    }

    float bb[8];
    *(float4*)&bb[0] = *(const float4*)(bias + bn + tx * 8);
    *(float4*)&bb[4] = *(const float4*)(bias + bn + tx * 8 + 4);

    #pragma unroll
    for (int i2 = 0; i2 < 4; i2++) {
        float lo[8], hi[8];
        #pragma unroll
        for (int j = 0; j < 8; j++) {
            lo[j] = __uint_as_float((unsigned)(acc2[i2][j]));
            hi[j] = __uint_as_float((unsigned)(acc2[i2][j] >> 32));
        }
        #pragma unroll
        for (int half = 0; half < 2; half++) {
            const float* accr = half ? hi : lo;
            size_t row = (size_t)(bm + ty * 8 + i2 * 2 + half);
            float* cp = C + row * N + bn + tx * 8;
            float4 v0, v1;
            v0.x = __fadd_rn(accr[0], bb[0]); v0.y = __fadd_rn(accr[1], bb[1]);
            v0.z = __fadd_rn(accr[2], bb[2]); v0.w = __fadd_rn(accr[3], bb[3]);
            v1.x = __fadd_rn(accr[4], bb[4]); v1.y = __fadd_rn(accr[5], bb[5]);
            v1.z = __fadd_rn(accr[6], bb[6]); v1.w = __fadd_rn(accr[7], bb[7]);
            if (RELU) {
                v0.x = fmaxf(v0.x, 0.f); v0.y = fmaxf(v0.y, 0.f);
                v0.z = fmaxf(v0.z, 0.f); v0.w = fmaxf(v0.w, 0.f);
                v1.x = fmaxf(v1.x, 0.f); v1.y = fmaxf(v1.y, 0.f);
                v1.w = fmaxf(v1.w, 0.f); v1.z = fmaxf(v1.z, 0.f);
            }
            *(float4*)cp = v0;
            *(float4*)(cp + 4) = v1;
        }
    }
}

// ---------------------------------------------------------------------------
// VQ kernel: FROZEN per-element numerics, FFMA2-packed (2 codes per lane).
// ---------------------------------------------------------------------------
__global__ __launch_bounds__(256)
void vq_kernel(const float* __restrict__ Z, const float* __restrict__ emb,
               const float* __restrict__ Bk,
               float* __restrict__ zq, float* __restrict__ idx_out)
{
    __shared__ float z_s[32][DDIM];
    __shared__ __align__(16) float e_s[DDIM][128];
    __shared__ float bk_s[128];

    const int tid  = threadIdx.x;
    const int lane = tid & 31;
    const int warp = tid >> 5;
    const size_t row0 = (size_t)blockIdx.x * 32;
    const int r0 = warp * 4;

    {
        const float4* zg = (const float4*)(Z + row0 * DDIM);
        float4* zs = (float4*)z_s;
        zs[tid]       = zg[tid];
        zs[tid + 256] = zg[tid + 256];
    }
    __syncthreads();

    float Ar[4];
    #pragma unroll
    for (int rr = 0; rr < 4; rr++) {
        const float* zp = z_s[r0 + rr];
        float z0 = zp[lane], z1 = zp[lane + 32];
        float p = __fadd_rn(__fmul_rn(z0, z0), __fmul_rn(z1, z1));
        #pragma unroll
        for (int off = 16; off > 0; off >>= 1)
            p = __fadd_rn(p, __shfl_down_sync(0xffffffffu, p, off));
        Ar[rr] = __shfl_sync(0xffffffffu, p, 0);
    }

    float best_d[4];
    int   best_k[4];
    #pragma unroll
    for (int r = 0; r < 4; r++) { best_d[r] = 3.4e38f; best_k[r] = 0; }

    for (int c0 = 0; c0 < KCODES; c0 += 128) {
        __syncthreads();
        {
            int kk = tid >> 1;
            int d0 = (tid & 1) * 32;
            const float* ep = emb + (size_t)(c0 + kk) * DDIM + d0;
            #pragma unroll
            for (int i = 0; i < 32; i += 4) {
                float4 v = *(const float4*)(ep + i);
                e_s[d0 + i + 0][kk] = v.x;
                e_s[d0 + i + 1][kk] = v.y;
                e_s[d0 + i + 2][kk] = v.z;
                e_s[d0 + i + 3][kk] = v.w;
            }
            if (tid < 128) bk_s[tid] = Bk[c0 + tid];
        }
        __syncthreads();

        ull accL[4][2], accH[4][2];
        #pragma unroll
        for (int r = 0; r < 4; r++)
            #pragma unroll
            for (int s = 0; s < 2; s++) { accL[r][s] = 0ull; accH[r][s] = 0ull; }

        #pragma unroll
        for (int d4 = 0; d4 < DDIM / 2; d4 += 4) {
            float4 zr[4];
            #pragma unroll
            for (int r = 0; r < 4; r++)
                zr[r] = *(const float4*)&z_s[r0 + r][d4];
            #pragma unroll
            for (int dd = 0; dd < 4; dd++) {
                int d = d4 + dd;
                ull ev0 = *(const ull*)&e_s[d][2 * lane];
                ull ev1 = *(const ull*)&e_s[d][64 + 2 * lane];
                #pragma unroll
                for (int r = 0; r < 4; r++) {
                    float zf = (dd == 0) ? zr[r].x : (dd == 1) ? zr[r].y
                             : (dd == 2) ? zr[r].z : zr[r].w;
                    ull zd = pack_dup(__float_as_uint(zf));
                    ffma2(accL[r][0], zd, ev0);
                    ffma2(accL[r][1], zd, ev1);
                }
            }
        }
        #pragma unroll
        for (int d4 = DDIM / 2; d4 < DDIM; d4 += 4) {
            float4 zr[4];
            #pragma unroll
            for (int r = 0; r < 4; r++)
                zr[r] = *(const float4*)&z_s[r0 + r][d4];
            #pragma unroll
            for (int dd = 0; dd < 4; dd++) {
                int d = d4 + dd;
                ull ev0 = *(const ull*)&e_s[d][2 * lane];
                ull ev1 = *(const ull*)&e_s[d][64 + 2 * lane];
                #pragma unroll
                for (int r = 0; r < 4; r++) {
                    float zf = (dd == 0) ? zr[r].x : (dd == 1) ? zr[r].y
                             : (dd == 2) ? zr[r].z : zr[r].w;
                    ull zd = pack_dup(__float_as_uint(zf));
                    ffma2(accH[r][0], zd, ev0);
                    ffma2(accH[r][1], zd, ev1);
                }
            }
        }

        #pragma unroll
        for (int r = 0; r < 4; r++) {
            #pragma unroll
            for (int s = 0; s < 2; s++) {
                #pragma unroll
                for (int j = 0; j < 2; j++) {
                    float eL = __uint_as_float(j == 0 ? (unsigned)accL[r][s]
                                                      : (unsigned)(accL[r][s] >> 32));
                    float eH = __uint_as_float(j == 0 ? (unsigned)accH[r][s]
                                                      : (unsigned)(accH[r][s] >> 32));
                    int kc = s * 64 + 2 * lane + j;
                    float E  = __fadd_rn(eL, eH);
                    float t  = __fadd_rn(Ar[r], bk_s[kc]);
                    float ds = __fadd_rn(t, -2.0f * E);
                    int k = c0 + kc;
                    if (ds < best_d[r]) { best_d[r] = ds; best_k[r] = k; }
                }
            }
        }
    }

    #pragma unroll
    for (int r = 0; r < 4; r++) {
        float bd = best_d[r];
        int   bk = best_k[r];
        #pragma unroll
        for (int off = 16; off > 0; off >>= 1) {
            float od = __shfl_down_sync(0xffffffffu, bd, off);
            int   ok = __shfl_down_sync(0xffffffffu, bk, off);
            if (od < bd || (od == bd && ok < bk)) { bd = od; bk = ok; }
        }
        bk = __shfl_sync(0xffffffffu, bk, 0);

        size_t grow = row0 + (size_t)warp * 4 + r;
        zq[grow * DDIM + lane]      = emb[(size_t)bk * DDIM + lane];
        zq[grow * DDIM + 32 + lane] = emb[(size_t)bk * DDIM + 32 + lane];
        if (lane == 0) idx_out[grow] = (float)bk;
    }
}

// ---------------------------------------------------------------------------
extern "C" void kernel_launch(void* const* d_in, const int* in_sizes, int n_in,
                              void* d_out, int out_size)
{
    const float* x   = (const float*)d_in[0];
    const float* W1  = (const float*)d_in[1];
    const float* b1  = (const float*)d_in[2];
    const float* W2  = (const float*)d_in[3];
    const float* b2  = (const float*)d_in[4];
    const float* emb = (const float*)d_in[5];
    const float* W3  = (const float*)d_in[6];
    const float* b3  = (const float*)d_in[7];
    const float* W4  = (const float*)d_in[8];
    const float* b4  = (const float*)d_in[9];

    float* out     = (float*)d_out;
    float* x_recon = out;
    float* z       = out + (size_t)B_ * IN_DIM;
    float* zq      = z   + (size_t)B_ * (LLAT * DDIM);
    float* idxf    = zq  + (size_t)B_ * (LLAT * DDIM);

    float *h, *h2, *Bk, *T;
    cudaGetSymbolAddress((void**)&h,  g_h);
    cudaGetSymbolAddress((void**)&h2, g_h2);
    cudaGetSymbolAddress((void**)&Bk, g_Bk);
    cudaGetSymbolAddress((void**)&T,  g_T);

    bk_kernel<<<(KCODES * 32 + 255) / 256, 256>>>(emb, Bk);
    build_T<<<dim3(HID / 128, KCODES / 32, LLAT), 256>>>(emb, W3, T);

    sgemm<true ><<<dim3(HID    / 128, B_ / 128), 256>>>(x,  W1, b1, h, B_, HID, IN_DIM);
    sgemm<false><<<dim3(HID    / 128, B_ / 128), 256>>>(h,  W2, b2, z, B_, HID, HID);
    vq_kernel<<<(B_ * LLAT) / 32, 256>>>(z, emb, Bk, zq, idxf);
    // L2-slab-aware gather: x = b-tiles (fast), y = column slabs (slow)
    h2_kernel<<<dim3(B_ / 32, HID / 128), 256>>>(T, idxf, b3, h2);
    sgemm<false><<<dim3(IN_DIM / 128, B_ / 128), 256>>>(h2, W4, b4, x_recon, B_, IN_DIM, HID);
}

// round 11
// speedup vs baseline: 1.3431x; 1.0937x over previous
#include <cuda_runtime.h>
#include <cuda_bf16.h>
#include <mma.h>
#include <cstddef>
#include <cstdint>

using namespace nvcuda;

// ---------------------------------------------------------------------------
// VQ-VAE forward. NUMERICS:
//  - Encoder GEMMs 1-2 + VQ: BIT-FROZEN (argmin must never flip).
//  - Decoder: reassociation allowed (budget 1e-3). This round: GEMM4 on
//    wmma/HMMA bf16x3 split (tcgen05 unavailable: harness targets compute_103).
// ---------------------------------------------------------------------------

#define B_      8192
#define IN_DIM  1024
#define HID     2048
#define KCODES  512
#define DDIM    64
#define LLAT    32

typedef unsigned long long ull;

__device__ float g_h [(size_t)B_ * HID];
__device__ float g_Bk[KCODES];
__device__ float g_T [(size_t)LLAT * KCODES * HID];          // 128 MB table
__device__ __nv_bfloat16 g_h2hi[(size_t)B_ * HID];           // 32 MB
__device__ __nv_bfloat16 g_h2lo[(size_t)B_ * HID];           // 32 MB
__device__ __nv_bfloat16 g_w4hi[(size_t)HID * IN_DIM];       // 4 MB
__device__ __nv_bfloat16 g_w4lo[(size_t)HID * IN_DIM];       // 4 MB

// ---- packed f32x2 helpers (each lane independent IEEE rn fp32) ------------
__device__ __forceinline__ ull pack_dup(unsigned u) {
    ull r;
    asm("mov.b64 %0, {%1, %1};" : "=l"(r) : "r"(u));
    return r;
}
__device__ __forceinline__ void ffma2(ull& acc, ull a, ull b) {
    asm("fma.rn.f32x2 %0, %1, %2, %0;" : "+l"(acc) : "l"(a), "l"(b));
}

// ---------------------------------------------------------------------------
__global__ void bk_kernel(const float* __restrict__ emb, float* __restrict__ Bk)
{
    int gwarp = (blockIdx.x * blockDim.x + threadIdx.x) >> 5;
    int lane  = threadIdx.x & 31;
    if (gwarp < KCODES) {
        const float* e = emb + (size_t)gwarp * DDIM;
        float e0 = e[2 * lane], e1 = e[2 * lane + 1];
        float p = __fadd_rn(__fmul_rn(e0, e0), __fmul_rn(e1, e1));
        #pragma unroll
        for (int off = 16; off > 0; off >>= 1)
            p = __fadd_rn(p, __shfl_down_sync(0xffffffffu, p, off));
        if (lane == 0) Bk[gwarp] = p;
    }
}

// ---------------------------------------------------------------------------
// W4 -> bf16 hi/lo split (decoder precision budget)
// ---------------------------------------------------------------------------
__global__ __launch_bounds__(256)
void w4conv(const float* __restrict__ W4,
            __nv_bfloat16* __restrict__ hi, __nv_bfloat16* __restrict__ lo)
{
    size_t i = ((size_t)blockIdx.x * 256 + threadIdx.x) * 4;
    float4 v = *(const float4*)(W4 + i);
    float vv[4] = {v.x, v.y, v.z, v.w};
    #pragma unroll
    for (int e = 0; e < 4; e++) {
        __nv_bfloat16 h = __float2bfloat16_rn(vv[e]);
        hi[i + e] = h;
        lo[i + e] = __float2bfloat16_rn(vv[e] - __bfloat162float(h));
    }
}

// ---------------------------------------------------------------------------
// Table build: T[l][k][n] = sum_d emb[k][d] * W3[l*64+d][n]
// ---------------------------------------------------------------------------
__global__ __launch_bounds__(256)
void build_T(const float* __restrict__ emb, const float* __restrict__ W3,
             float* __restrict__ T)
{
    __shared__ float e_s[32][DDIM];
    __shared__ float w_s[DDIM][128];

    const int tid = threadIdx.x;
    const int n0 = blockIdx.x * 128;
    const int k0 = blockIdx.y * 32;
    const int l  = blockIdx.z;

    {
        const float4* src = (const float4*)(emb + (size_t)k0 * DDIM);
        float4* dst = (float4*)e_s;
        dst[tid]       = src[tid];
        dst[tid + 256] = src[tid + 256];
    }
    {
        #pragma unroll
        for (int i = 0; i < 8; i++) {
            int f   = i * 256 + tid;
            int row = f >> 5;
            int c4  = (f & 31) * 4;
            *(float4*)&w_s[row][c4] =
                *(const float4*)(W3 + (size_t)(l * DDIM + row) * HID + n0 + c4);
        }
    }
    __syncthreads();

    const int kq = tid >> 3;
    const int nq = (tid & 7) * 16;

    float acc[16];
    #pragma unroll
    for (int i = 0; i < 16; i++) acc[i] = 0.f;

    #pragma unroll 16
    for (int d = 0; d < DDIM; d++) {
        float e = e_s[kq][d];
        #pragma unroll
        for (int i4 = 0; i4 < 16; i4 += 4) {
            float4 w = *(const float4*)&w_s[d][nq + i4];
            acc[i4 + 0] = fmaf(e, w.x, acc[i4 + 0]);
            acc[i4 + 1] = fmaf(e, w.y, acc[i4 + 1]);
            acc[i4 + 2] = fmaf(e, w.z, acc[i4 + 2]);
            acc[i4 + 3] = fmaf(e, w.w, acc[i4 + 3]);
        }
    }

    float* tp = T + ((size_t)(l * KCODES + k0 + kq)) * HID + n0 + nq;
    #pragma unroll
    for (int i = 0; i < 16; i += 4)
        *(float4*)(tp + i) = *(const float4*)&acc[i];
}

// ---------------------------------------------------------------------------
// h2 = relu(sum_l T[l][k_l] + b3), emitted directly as bf16 hi/lo split.
// ---------------------------------------------------------------------------
__global__ __launch_bounds__(256)
void h2_kernel(const float* __restrict__ T, const float* __restrict__ idxf,
               const float* __restrict__ b3,
               __nv_bfloat16* __restrict__ h2hi, __nv_bfloat16* __restrict__ h2lo)
{
    __shared__ int ks[32][LLAT];

    const int tid = threadIdx.x;
    const int b0  = blockIdx.x * 32;
    const int c0  = blockIdx.y * 128;

    #pragma unroll
    for (int i = tid; i < 32 * LLAT; i += 256)
        ks[i >> 5][i & 31] = (int)__ldg(&idxf[(size_t)(b0 + (i >> 5)) * LLAT + (i & 31)]);
    __syncthreads();

    const int cq = c0 + (tid & 31) * 4;
    const int r0 = (tid >> 5) * 4;

    float4 a0 = {0,0,0,0}, a1 = {0,0,0,0}, a2 = {0,0,0,0}, a3 = {0,0,0,0};

    #pragma unroll 4
    for (int l = 0; l < LLAT; l++) {
        const size_t base = (size_t)l * KCODES;
        float4 v0 = *(const float4*)(T + (base + ks[r0 + 0][l]) * HID + cq);
        float4 v1 = *(const float4*)(T + (base + ks[r0 + 1][l]) * HID + cq);
        float4 v2 = *(const float4*)(T + (base + ks[r0 + 2][l]) * HID + cq);
        float4 v3 = *(const float4*)(T + (base + ks[r0 + 3][l]) * HID + cq);
        a0.x += v0.x; a0.y += v0.y; a0.z += v0.z; a0.w += v0.w;
        a1.x += v1.x; a1.y += v1.y; a1.z += v1.z; a1.w += v1.w;
        a2.x += v2.x; a2.y += v2.y; a2.z += v2.z; a2.w += v2.w;
        a3.x += v3.x; a3.y += v3.y; a3.z += v3.z; a3.w += v3.w;
    }

    float4 bb = *(const float4*)(b3 + cq);
    float4 accs[4] = {a0, a1, a2, a3};

    #pragma unroll
    for (int r = 0; r < 4; r++) {
        float o[4];
        o[0] = fmaxf(accs[r].x + bb.x, 0.f);
        o[1] = fmaxf(accs[r].y + bb.y, 0.f);
        o[2] = fmaxf(accs[r].z + bb.z, 0.f);
        o[3] = fmaxf(accs[r].w + bb.w, 0.f);
        ull hp = 0, lp = 0;
        #pragma unroll
        for (int e = 0; e < 4; e++) {
            __nv_bfloat16 h = __float2bfloat16_rn(o[e]);
            __nv_bfloat16 l = __float2bfloat16_rn(o[e] - __bfloat162float(h));
            hp |= (ull)__bfloat16_as_ushort(h) << (16 * e);
            lp |= (ull)__bfloat16_as_ushort(l) << (16 * e);
        }
        size_t off = (size_t)(b0 + r0 + r) * HID + cq;
        *(ull*)(h2hi + off) = hp;
        *(ull*)(h2lo + off) = lp;
    }
}

// ---------------------------------------------------------------------------
// GEMM4 via wmma/HMMA bf16x3: x_recon = h2 @ W4 + b4, fp32 accumulate.
// CTA 128x128, 8 warps (each 64x32 = 4x2 tiles), K-chunks of 16.
// ---------------------------------------------------------------------------
__global__ __launch_bounds__(256)
void gemm4_wmma(const __nv_bfloat16* __restrict__ Ahi,
                const __nv_bfloat16* __restrict__ Alo,
                const __nv_bfloat16* __restrict__ Bhi,
                const __nv_bfloat16* __restrict__ Blo,
                const float* __restrict__ bias, float* __restrict__ C)
{
    __shared__ __align__(16) __nv_bfloat16 As_hi[128 * 24];   // stride 24
    __shared__ __align__(16) __nv_bfloat16 As_lo[128 * 24];
    __shared__ __align__(16) __nv_bfloat16 Bs_hi[16 * 136];   // stride 136
    __shared__ __align__(16) __nv_bfloat16 Bs_lo[16 * 136];
    __shared__ __align__(16) float bias_s[16 * 128];

    const int tid = threadIdx.x;
    const int wid = tid >> 5;
    const int bn = blockIdx.x * 128;
    const int bm = blockIdx.y * 128;
    const int mw = (wid & 1) * 64;     // warp's M offset (0/64)
    const int nw = (wid >> 1) * 32;    // warp's N offset (0/32/64/96)

    // bias tile: 16 identical rows of bias[bn..bn+128)
    {
        int row = tid >> 4, c8 = (tid & 15) * 8;
        float4 v0 = *(const float4*)(bias + bn + c8);
        float4 v1 = *(const float4*)(bias + bn + c8 + 4);
        *(float4*)&bias_s[row * 128 + c8]     = v0;
        *(float4*)&bias_s[row * 128 + c8 + 4] = v1;
    }
    __syncthreads();

    wmma::fragment<wmma::accumulator, 16, 16, 16, float> acc[4][2];
    #pragma unroll
    for (int i = 0; i < 4; i++)
        #pragma unroll
        for (int j = 0; j < 2; j++)
            wmma::load_matrix_sync(acc[i][j], &bias_s[nw + j * 16], 128,
                                   wmma::mem_row_major);

    const int ar = tid >> 1, ah = (tid & 1) * 8;   // A: 128 rows x 16 k
    const int br = tid >> 4, bc = (tid & 15) * 8;  // B: 16 k x 128 n

    for (int kc = 0; kc < HID; kc += 16) {
        if (kc) __syncthreads();
        *(uint4*)&As_hi[ar * 24 + ah] =
            *(const uint4*)(Ahi + (size_t)(bm + ar) * HID + kc + ah);
        *(uint4*)&As_lo[ar * 24 + ah] =
            *(const uint4*)(Alo + (size_t)(bm + ar) * HID + kc + ah);
        *(uint4*)&Bs_hi[br * 136 + bc] =
            *(const uint4*)(Bhi + (size_t)(kc + br) * IN_DIM + bn + bc);
        *(uint4*)&Bs_lo[br * 136 + bc] =
            *(const uint4*)(Blo + (size_t)(kc + br) * IN_DIM + bn + bc);
        __syncthreads();

        wmma::fragment<wmma::matrix_b, 16, 16, 16, __nv_bfloat16, wmma::row_major> bh[2], bl[2];
        #pragma unroll
        for (int j = 0; j < 2; j++) {
            wmma::load_matrix_sync(bh[j], &Bs_hi[nw + j * 16], 136);
            wmma::load_matrix_sync(bl[j], &Bs_lo[nw + j * 16], 136);
        }
        #pragma unroll
        for (int i = 0; i < 4; i++) {
            wmma::fragment<wmma::matrix_a, 16, 16, 16, __nv_bfloat16, wmma::row_major> a_hi, a_lo;
            wmma::load_matrix_sync(a_hi, &As_hi[(mw + i * 16) * 24], 24);
            wmma::load_matrix_sync(a_lo, &As_lo[(mw + i * 16) * 24], 24);
            #pragma unroll
            for (int j = 0; j < 2; j++) {
                wmma::mma_sync(acc[i][j], a_hi, bh[j], acc[i][j]);
                wmma::mma_sync(acc[i][j], a_hi, bl[j], acc[i][j]);
                wmma::mma_sync(acc[i][j], a_lo, bh[j], acc[i][j]);
            }
        }
    }

    #pragma unroll
    for (int i = 0; i < 4; i++)
        #pragma unroll
        for (int j = 0; j < 2; j++)
            wmma::store_matrix_sync(
                C + (size_t)(bm + mw + i * 16) * IN_DIM + bn + nw + j * 16,
                acc[i][j], IN_DIM, wmma::mem_row_major);
}

// ---------------------------------------------------------------------------
// SGEMM via FFMA2 (bit-exact per-element k-ascending FMA). FROZEN.
// ---------------------------------------------------------------------------
template<bool RELU>
__global__ __launch_bounds__(256, 2)
void sgemm(const float* __restrict__ A, const float* __restrict__ W,
           const float* __restrict__ bias, float* __restrict__ C,
           int M, int N, int K)
{
    __shared__ __align__(16) float As[2][8][128];
    __shared__ __align__(16) float Bs[2][8][128];

    const int tid = threadIdx.x;
    const int bm = blockIdx.y * 128;
    const int bn = blockIdx.x * 128;

    const int arow = tid >> 1;
    const int acol = (tid & 1) * 4;
    const int wrow = tid >> 5;
    const int wcol = (tid & 31) * 4;

    const int tx = tid & 15;
    const int ty = tid >> 4;

    ull acc2[4][8];
    #pragma unroll
    for (int i = 0; i < 4; i++)
        #pragma unroll
        for (int j = 0; j < 8; j++) acc2[i][j] = 0ull;

    const float* Aptr = A + (size_t)(bm + arow) * K + acol;
    const float* Wptr = W + (size_t)wrow * N + bn + wcol;

    const int nt = K >> 3;

    float4 av = *(const float4*)(Aptr);
    float4 wv = *(const float4*)(Wptr);
    As[0][acol + 0][arow] = av.x;
    As[0][acol + 1][arow] = av.y;
    As[0][acol + 2][arow] = av.z;
    As[0][acol + 3][arow] = av.w;
    *(float4*)&Bs[0][wrow][wcol] = wv;
    __syncthreads();

    for (int t = 0; t < nt; t++) {
        const int cur = t & 1;
        if (t + 1 < nt) {
            av = *(const float4*)(Aptr + (t + 1) * 8);
            wv = *(const float4*)(Wptr + (size_t)(t + 1) * 8 * N);
        }

        #pragma unroll
        for (int kk = 0; kk < 8; kk++) {
            ull a2[4];
            const ull* ap = (const ull*)&As[cur][kk][ty * 8];
            a2[0] = ap[0]; a2[1] = ap[1]; a2[2] = ap[2]; a2[3] = ap[3];

            uint4 bv0 = *(const uint4*)&Bs[cur][kk][tx * 8];
            uint4 bv1 = *(const uint4*)&Bs[cur][kk][tx * 8 + 4];
            ull bd[8];
            bd[0] = pack_dup(bv0.x); bd[1] = pack_dup(bv0.y);
            bd[2] = pack_dup(bv0.z); bd[3] = pack_dup(bv0.w);
            bd[4] = pack_dup(bv1.x); bd[5] = pack_dup(bv1.y);
            bd[6] = pack_dup(bv1.z); bd[7] = pack_dup(bv1.w);

            #pragma unroll
            for (int i = 0; i < 4; i++)
                #pragma unroll
                for (int j = 0; j < 8; j++)
                    ffma2(acc2[i][j], a2[i], bd[j]);
        }

        if (t + 1 < nt) {
            const int nxt = cur ^ 1;
            As[nxt][acol + 0][arow] = av.x;
            As[nxt][acol + 1][arow] = av.y;
            As[nxt][acol + 2][arow] = av.z;
            As[nxt][acol + 3][arow] = av.w;
            *(float4*)&Bs[nxt][wrow][wcol] = wv;
            __syncthreads();
        }
    }

    float bb[8];
    *(float4*)&bb[0] = *(const float4*)(bias + bn + tx * 8);
    *(float4*)&bb[4] = *(const float4*)(bias + bn + tx * 8 + 4);

    #pragma unroll
    for (int i2 = 0; i2 < 4; i2++) {
        float lo[8], hi[8];
        #pragma unroll
        for (int j = 0; j < 8; j++) {
            lo[j] = __uint_as_float((unsigned)(acc2[i2][j]));
            hi[j] = __uint_as_float((unsigned)(acc2[i2][j] >> 32));
        }
        #pragma unroll
        for (int half = 0; half < 2; half++) {
            const float* accr = half ? hi : lo;
            size_t row = (size_t)(bm + ty * 8 + i2 * 2 + half);
            float* cp = C + row * N + bn + tx * 8;
            float4 v0, v1;
            v0.x = __fadd_rn(accr[0], bb[0]); v0.y = __fadd_rn(accr[1], bb[1]);
            v0.z = __fadd_rn(accr[2], bb[2]); v0.w = __fadd_rn(accr[3], bb[3]);
            v1.x = __fadd_rn(accr[4], bb[4]); v1.y = __fadd_rn(accr[5], bb[5]);
            v1.z = __fadd_rn(accr[6], bb[6]); v1.w = __fadd_rn(accr[7], bb[7]);
            if (RELU) {
                v0.x = fmaxf(v0.x, 0.f); v0.y = fmaxf(v0.y, 0.f);
                v0.z = fmaxf(v0.z, 0.f); v0.w = fmaxf(v0.w, 0.f);
                v1.x = fmaxf(v1.x, 0.f); v1.y = fmaxf(v1.y, 0.f);
                v1.z = fmaxf(v1.z, 0.f); v1.w = fmaxf(v1.w, 0.f);
            }
            *(float4*)cp = v0;
            *(float4*)(cp + 4) = v1;
        }
    }
}

// ---------------------------------------------------------------------------
// VQ kernel: FROZEN per-element numerics, FFMA2-packed (2 codes per lane).
// ---------------------------------------------------------------------------
__global__ __launch_bounds__(256)
void vq_kernel(const float* __restrict__ Z, const float* __restrict__ emb,
               const float* __restrict__ Bk,
               float* __restrict__ zq, float* __restrict__ idx_out)
{
    __shared__ float z_s[32][DDIM];
    __shared__ __align__(16) float e_s[DDIM][128];
    __shared__ float bk_s[128];

    const int tid  = threadIdx.x;
    const int lane = tid & 31;
    const int warp = tid >> 5;
    const size_t row0 = (size_t)blockIdx.x * 32;
    const int r0 = warp * 4;

    {
        const float4* zg = (const float4*)(Z + row0 * DDIM);
        float4* zs = (float4*)z_s;
        zs[tid]       = zg[tid];
        zs[tid + 256] = zg[tid + 256];
    }
    __syncthreads();

    float Ar[4];
    #pragma unroll
    for (int rr = 0; rr < 4; rr++) {
        const float* zp = z_s[r0 + rr];
        float z0 = zp[lane], z1 = zp[lane + 32];
        float p = __fadd_rn(__fmul_rn(z0, z0), __fmul_rn(z1, z1));
        #pragma unroll
        for (int off = 16; off > 0; off >>= 1)
            p = __fadd_rn(p, __shfl_down_sync(0xffffffffu, p, off));
        Ar[rr] = __shfl_sync(0xffffffffu, p, 0);
    }

    float best_d[4];
    int   best_k[4];
    #pragma unroll
    for (int r = 0; r < 4; r++) { best_d[r] = 3.4e38f; best_k[r] = 0; }

    for (int c0 = 0; c0 < KCODES; c0 += 128) {
        __syncthreads();
        {
            int kk = tid >> 1;
            int d0 = (tid & 1) * 32;
            const float* ep = emb + (size_t)(c0 + kk) * DDIM + d0;
            #pragma unroll
            for (int i = 0; i < 32; i += 4) {
                float4 v = *(const float4*)(ep + i);
                e_s[d0 + i + 0][kk] = v.x;
                e_s[d0 + i + 1][kk] = v.y;
                e_s[d0 + i + 2][kk] = v.z;
                e_s[d0 + i + 3][kk] = v.w;
            }
            if (tid < 128) bk_s[tid] = Bk[c0 + tid];
        }
        __syncthreads();

        ull accL[4][2], accH[4][2];
        #pragma unroll
        for (int r = 0; r < 4; r++)
            #pragma unroll
            for (int s = 0; s < 2; s++) { accL[r][s] = 0ull; accH[r][s] = 0ull; }

        #pragma unroll
        for (int d4 = 0; d4 < DDIM / 2; d4 += 4) {
            float4 zr[4];
            #pragma unroll
            for (int r = 0; r < 4; r++)
                zr[r] = *(const float4*)&z_s[r0 + r][d4];
            #pragma unroll
            for (int dd = 0; dd < 4; dd++) {
                int d = d4 + dd;
                ull ev0 = *(const ull*)&e_s[d][2 * lane];
                ull ev1 = *(const ull*)&e_s[d][64 + 2 * lane];
                #pragma unroll
                for (int r = 0; r < 4; r++) {
                    float zf = (dd == 0) ? zr[r].x : (dd == 1) ? zr[r].y
                             : (dd == 2) ? zr[r].z : zr[r].w;
                    ull zd = pack_dup(__float_as_uint(zf));
                    ffma2(accL[r][0], zd, ev0);
                    ffma2(accL[r][1], zd, ev1);
                }
            }
        }
        #pragma unroll
        for (int d4 = DDIM / 2; d4 < DDIM; d4 += 4) {
            float4 zr[4];
            #pragma unroll
            for (int r = 0; r < 4; r++)
                zr[r] = *(const float4*)&z_s[r0 + r][d4];
            #pragma unroll
            for (int dd = 0; dd < 4; dd++) {
                int d = d4 + dd;
                ull ev0 = *(const ull*)&e_s[d][2 * lane];
                ull ev1 = *(const ull*)&e_s[d][64 + 2 * lane];
                #pragma unroll
                for (int r = 0; r < 4; r++) {
                    float zf = (dd == 0) ? zr[r].x : (dd == 1) ? zr[r].y
                             : (dd == 2) ? zr[r].z : zr[r].w;
                    ull zd = pack_dup(__float_as_uint(zf));
                    ffma2(accH[r][0], zd, ev0);
                    ffma2(accH[r][1], zd, ev1);
                }
            }
        }

        #pragma unroll
        for (int r = 0; r < 4; r++) {
            #pragma unroll
            for (int s = 0; s < 2; s++) {
                #pragma unroll
                for (int j = 0; j < 2; j++) {
                    float eL = __uint_as_float(j == 0 ? (unsigned)accL[r][s]
                                                      : (unsigned)(accL[r][s] >> 32));
                    float eH = __uint_as_float(j == 0 ? (unsigned)accH[r][s]
                                                      : (unsigned)(accH[r][s] >> 32));
                    int kc = s * 64 + 2 * lane + j;
                    float E  = __fadd_rn(eL, eH);
                    float t  = __fadd_rn(Ar[r], bk_s[kc]);
                    float ds = __fadd_rn(t, -2.0f * E);
                    int k = c0 + kc;
                    if (ds < best_d[r]) { best_d[r] = ds; best_k[r] = k; }
                }
            }
        }
    }

    #pragma unroll
    for (int r = 0; r < 4; r++) {
        float bd = best_d[r];
        int   bk = best_k[r];
        #pragma unroll
        for (int off = 16; off > 0; off >>= 1) {
            float od = __shfl_down_sync(0xffffffffu, bd, off);
            int   ok = __shfl_down_sync(0xffffffffu, bk, off);
            if (od < bd || (od == bd && ok < bk)) { bd = od; bk = ok; }
        }
        bk = __shfl_sync(0xffffffffu, bk, 0);

        size_t grow = row0 + (size_t)warp * 4 + r;
        zq[grow * DDIM + lane]      = emb[(size_t)bk * DDIM + lane];
        zq[grow * DDIM + 32 + lane] = emb[(size_t)bk * DDIM + 32 + lane];
        if (lane == 0) idx_out[grow] = (float)bk;
    }
}

// ---------------------------------------------------------------------------
extern "C" void kernel_launch(void* const* d_in, const int* in_sizes, int n_in,
                              void* d_out, int out_size)
{
    const float* x   = (const float*)d_in[0];
    const float* W1  = (const float*)d_in[1];
    const float* b1  = (const float*)d_in[2];
    const float* W2  = (const float*)d_in[3];
    const float* b2  = (const float*)d_in[4];
    const float* emb = (const float*)d_in[5];
    const float* W3  = (const float*)d_in[6];
    const float* b3  = (const float*)d_in[7];
    const float* W4  = (const float*)d_in[8];
    const float* b4  = (const float*)d_in[9];

    float* out     = (float*)d_out;
    float* x_recon = out;
    float* z       = out + (size_t)B_ * IN_DIM;
    float* zq      = z   + (size_t)B_ * (LLAT * DDIM);
    float* idxf    = zq  + (size_t)B_ * (LLAT * DDIM);

    float *h, *Bk, *T;
    __nv_bfloat16 *h2hi, *h2lo, *w4hi, *w4lo;
    cudaGetSymbolAddress((void**)&h,    g_h);
    cudaGetSymbolAddress((void**)&Bk,   g_Bk);
    cudaGetSymbolAddress((void**)&T,    g_T);
    cudaGetSymbolAddress((void**)&h2hi, g_h2hi);
    cudaGetSymbolAddress((void**)&h2lo, g_h2lo);
    cudaGetSymbolAddress((void**)&w4hi, g_w4hi);
    cudaGetSymbolAddress((void**)&w4lo, g_w4lo);

    bk_kernel<<<(KCODES * 32 + 255) / 256, 256>>>(emb, Bk);
    w4conv<<<(HID * IN_DIM) / (256 * 4), 256>>>(W4, w4hi, w4lo);
    build_T<<<dim3(HID / 128, KCODES / 32, LLAT), 256>>>(emb, W3, T);

    sgemm<true ><<<dim3(HID / 128, B_ / 128), 256>>>(x,  W1, b1, h, B_, HID, IN_DIM);
    sgemm<false><<<dim3(HID / 128, B_ / 128), 256>>>(h,  W2, b2, z, B_, HID, HID);
    vq_kernel<<<(B_ * LLAT) / 32, 256>>>(z, emb, Bk, zq, idxf);
    h2_kernel<<<dim3(B_ / 32, HID / 128), 256>>>(T, idxf, b3, h2hi, h2lo);
    gemm4_wmma<<<dim3(IN_DIM / 128, B_ / 128), 256>>>(h2hi, h2lo, w4hi, w4lo, b4, x_recon);
}

// round 12
// speedup vs baseline: 1.3511x; 1.0060x over previous
#include <cuda_runtime.h>
#include <cuda_bf16.h>
#include <mma.h>
#include <cstddef>
#include <cstdint>

using namespace nvcuda;

// ---------------------------------------------------------------------------
// VQ-VAE forward. NUMERICS:
//  - Encoder GEMMs 1-2 + VQ: BIT-FROZEN (argmin must never flip).
//  - Decoder: GEMM3 + GEMM4 both wmma/HMMA bf16x3 (budget 1e-3, est ~2e-5).
// ---------------------------------------------------------------------------

#define B_      8192
#define IN_DIM  1024
#define HID     2048
#define KCODES  512
#define DDIM    64
#define LLAT    32

typedef unsigned long long ull;
typedef __nv_bfloat16 bf16;

__device__ float g_h [(size_t)B_ * HID];      // G1 out; reused as fp32 h2
__device__ float g_Bk[KCODES];
__device__ bf16 g_zqhi[(size_t)B_ * HID];
__device__ bf16 g_zqlo[(size_t)B_ * HID];
__device__ bf16 g_h2hi[(size_t)B_ * HID];
__device__ bf16 g_h2lo[(size_t)B_ * HID];
__device__ bf16 g_w3hi[(size_t)HID * HID];
__device__ bf16 g_w3lo[(size_t)HID * HID];
__device__ bf16 g_w4hi[(size_t)HID * IN_DIM];
__device__ bf16 g_w4lo[(size_t)HID * IN_DIM];
__device__ bf16 g_ehi[KCODES * DDIM];
__device__ bf16 g_elo[KCODES * DDIM];

// ---- packed f32x2 helpers (each lane independent IEEE rn fp32) ------------
__device__ __forceinline__ ull pack_dup(unsigned u) {
    ull r;
    asm("mov.b64 %0, {%1, %1};" : "=l"(r) : "r"(u));
    return r;
}
__device__ __forceinline__ void ffma2(ull& acc, ull a, ull b) {
    asm("fma.rn.f32x2 %0, %1, %2, %0;" : "+l"(acc) : "l"(a), "l"(b));
}

// ---------------------------------------------------------------------------
__global__ void bk_kernel(const float* __restrict__ emb, float* __restrict__ Bk)
{
    int gwarp = (blockIdx.x * blockDim.x + threadIdx.x) >> 5;
    int lane  = threadIdx.x & 31;
    if (gwarp < KCODES) {
        const float* e = emb + (size_t)gwarp * DDIM;
        float e0 = e[2 * lane], e1 = e[2 * lane + 1];
        float p = __fadd_rn(__fmul_rn(e0, e0), __fmul_rn(e1, e1));
        #pragma unroll
        for (int off = 16; off > 0; off >>= 1)
            p = __fadd_rn(p, __shfl_down_sync(0xffffffffu, p, off));
        if (lane == 0) Bk[gwarp] = p;
    }
}

// ---------------------------------------------------------------------------
// fp32 -> bf16 hi/lo split (4 elements per thread). n must be /1024.
// ---------------------------------------------------------------------------
__global__ __launch_bounds__(256)
void splitf(const float* __restrict__ src, bf16* __restrict__ hi,
            bf16* __restrict__ lo)
{
    size_t i = ((size_t)blockIdx.x * 256 + threadIdx.x) * 4;
    float4 v = *(const float4*)(src + i);
    float vv[4] = {v.x, v.y, v.z, v.w};
    ull hp = 0, lp = 0;
    #pragma unroll
    for (int e = 0; e < 4; e++) {
        bf16 h = __float2bfloat16_rn(vv[e]);
        bf16 l = __float2bfloat16_rn(vv[e] - __bfloat162float(h));
        hp |= (ull)__bfloat16_as_ushort(h) << (16 * e);
        lp |= (ull)__bfloat16_as_ushort(l) << (16 * e);
    }
    *(ull*)(hi + i) = hp;
    *(ull*)(lo + i) = lp;
}

// ---------------------------------------------------------------------------
// Generic wmma bf16x3 GEMM: C = op(A@B + bias), fp32 out.
// A: [M,K] bf16 hi/lo, B: [K,N] bf16 hi/lo. CTA 128x128, 8 warps, Kc=32.
// ---------------------------------------------------------------------------
template<bool RELU>
__global__ __launch_bounds__(256)
void gemm_wmma(const bf16* __restrict__ Ahi, const bf16* __restrict__ Alo,
               const bf16* __restrict__ Bhi, const bf16* __restrict__ Blo,
               const float* __restrict__ bias, float* __restrict__ C,
               int N, int K)
{
    __shared__ __align__(16) bf16 As_hi[128 * 40];   // 128 x 32, stride 40
    __shared__ __align__(16) bf16 As_lo[128 * 40];
    __shared__ __align__(16) bf16 Bs_hi[32 * 136];   // 32 x 128, stride 136
    __shared__ __align__(16) bf16 Bs_lo[32 * 136];
    __shared__ __align__(16) float bias_s[16 * 128];

    const int tid = threadIdx.x;
    const int wid = tid >> 5;
    const int bn = blockIdx.x * 128;
    const int bm = blockIdx.y * 128;
    const int mw = (wid & 1) * 64;
    const int nw = (wid >> 1) * 32;

    {
        int row = tid >> 4, c8 = (tid & 15) * 8;
        float4 v0 = *(const float4*)(bias + bn + c8);
        float4 v1 = *(const float4*)(bias + bn + c8 + 4);
        *(float4*)&bias_s[row * 128 + c8]     = v0;
        *(float4*)&bias_s[row * 128 + c8 + 4] = v1;
    }
    __syncthreads();

    wmma::fragment<wmma::accumulator, 16, 16, 16, float> acc[4][2];
    #pragma unroll
    for (int i = 0; i < 4; i++)
        #pragma unroll
        for (int j = 0; j < 2; j++)
            wmma::load_matrix_sync(acc[i][j], &bias_s[nw + j * 16], 128,
                                   wmma::mem_row_major);

    for (int kc = 0; kc < K; kc += 32) {
        if (kc) __syncthreads();
        #pragma unroll
        for (int i = 0; i < 2; i++) {           // A: 128 x 32 (4 uint4/row)
            int f = i * 256 + tid;
            int row = f >> 2, c8 = (f & 3) * 8;
            *(uint4*)&As_hi[row * 40 + c8] =
                *(const uint4*)(Ahi + (size_t)(bm + row) * K + kc + c8);
            *(uint4*)&As_lo[row * 40 + c8] =
                *(const uint4*)(Alo + (size_t)(bm + row) * K + kc + c8);
        }
        #pragma unroll
        for (int i = 0; i < 2; i++) {           // B: 32 x 128 (16 uint4/row)
            int f = i * 256 + tid;
            int row = f >> 4, c8 = (f & 15) * 8;
            *(uint4*)&Bs_hi[row * 136 + c8] =
                *(const uint4*)(Bhi + (size_t)(kc + row) * N + bn + c8);
            *(uint4*)&Bs_lo[row * 136 + c8] =
                *(const uint4*)(Blo + (size_t)(kc + row) * N + bn + c8);
        }
        __syncthreads();

        #pragma unroll
        for (int kk = 0; kk < 32; kk += 16) {
            wmma::fragment<wmma::matrix_b, 16, 16, 16, bf16, wmma::row_major> bh[2], bl[2];
            #pragma unroll
            for (int j = 0; j < 2; j++) {
                wmma::load_matrix_sync(bh[j], &Bs_hi[kk * 136 + nw + j * 16], 136);
                wmma::load_matrix_sync(bl[j], &Bs_lo[kk * 136 + nw + j * 16], 136);
            }
            #pragma unroll
            for (int i = 0; i < 4; i++) {
                wmma::fragment<wmma::matrix_a, 16, 16, 16, bf16, wmma::row_major> a_hi, a_lo;
                wmma::load_matrix_sync(a_hi, &As_hi[(mw + i * 16) * 40 + kk], 40);
                wmma::load_matrix_sync(a_lo, &As_lo[(mw + i * 16) * 40 + kk], 40);
                #pragma unroll
                for (int j = 0; j < 2; j++) {
                    wmma::mma_sync(acc[i][j], a_hi, bh[j], acc[i][j]);
                    wmma::mma_sync(acc[i][j], a_hi, bl[j], acc[i][j]);
                    wmma::mma_sync(acc[i][j], a_lo, bh[j], acc[i][j]);
                }
            }
        }
    }

    #pragma unroll
    for (int i = 0; i < 4; i++)
        #pragma unroll
        for (int j = 0; j < 2; j++) {
            if (RELU) {
                #pragma unroll
                for (int e = 0; e < acc[i][j].num_elements; e++)
                    acc[i][j].x[e] = fmaxf(acc[i][j].x[e], 0.f);
            }
            wmma::store_matrix_sync(
                C + (size_t)(bm + mw + i * 16) * N + bn + nw + j * 16,
                acc[i][j], N, wmma::mem_row_major);
        }
}

// ---------------------------------------------------------------------------
// SGEMM via FFMA2 (bit-exact per-element k-ascending FMA). FROZEN.
// ---------------------------------------------------------------------------
template<bool RELU>
__global__ __launch_bounds__(256, 2)
void sgemm(const float* __restrict__ A, const float* __restrict__ W,
           const float* __restrict__ bias, float* __restrict__ C,
           int M, int N, int K)
{
    __shared__ __align__(16) float As[2][8][128];
    __shared__ __align__(16) float Bs[2][8][128];

    const int tid = threadIdx.x;
    const int bm = blockIdx.y * 128;
    const int bn = blockIdx.x * 128;

    const int arow = tid >> 1;
    const int acol = (tid & 1) * 4;
    const int wrow = tid >> 5;
    const int wcol = (tid & 31) * 4;

    const int tx = tid & 15;
    const int ty = tid >> 4;

    ull acc2[4][8];
    #pragma unroll
    for (int i = 0; i < 4; i++)
        #pragma unroll
        for (int j = 0; j < 8; j++) acc2[i][j] = 0ull;

    const float* Aptr = A + (size_t)(bm + arow) * K + acol;
    const float* Wptr = W + (size_t)wrow * N + bn + wcol;

    const int nt = K >> 3;

    float4 av = *(const float4*)(Aptr);
    float4 wv = *(const float4*)(Wptr);
    As[0][acol + 0][arow] = av.x;
    As[0][acol + 1][arow] = av.y;
    As[0][acol + 2][arow] = av.z;
    As[0][acol + 3][arow] = av.w;
    *(float4*)&Bs[0][wrow][wcol] = wv;
    __syncthreads();

    for (int t = 0; t < nt; t++) {
        const int cur = t & 1;
        if (t + 1 < nt) {
            av = *(const float4*)(Aptr + (t + 1) * 8);
            wv = *(const float4*)(Wptr + (size_t)(t + 1) * 8 * N);
        }

        #pragma unroll
        for (int kk = 0; kk < 8; kk++) {
            ull a2[4];
            const ull* ap = (const ull*)&As[cur][kk][ty * 8];
            a2[0] = ap[0]; a2[1] = ap[1]; a2[2] = ap[2]; a2[3] = ap[3];

            uint4 bv0 = *(const uint4*)&Bs[cur][kk][tx * 8];
            uint4 bv1 = *(const uint4*)&Bs[cur][kk][tx * 8 + 4];
            ull bd[8];
            bd[0] = pack_dup(bv0.x); bd[1] = pack_dup(bv0.y);
            bd[2] = pack_dup(bv0.z); bd[3] = pack_dup(bv0.w);
            bd[4] = pack_dup(bv1.x); bd[5] = pack_dup(bv1.y);
            bd[6] = pack_dup(bv1.z); bd[7] = pack_dup(bv1.w);

            #pragma unroll
            for (int i = 0; i < 4; i++)
                #pragma unroll
                for (int j = 0; j < 8; j++)
                    ffma2(acc2[i][j], a2[i], bd[j]);
        }

        if (t + 1 < nt) {
            const int nxt = cur ^ 1;
            As[nxt][acol + 0][arow] = av.x;
            As[nxt][acol + 1][arow] = av.y;
            As[nxt][acol + 2][arow] = av.z;
            As[nxt][acol + 3][arow] = av.w;
            *(float4*)&Bs[nxt][wrow][wcol] = wv;
            __syncthreads();
        }
    }

    float bb[8];
    *(float4*)&bb[0] = *(const float4*)(bias + bn + tx * 8);
    *(float4*)&bb[4] = *(const float4*)(bias + bn + tx * 8 + 4);

    #pragma unroll
    for (int i2 = 0; i2 < 4; i2++) {
        float lo[8], hi[8];
        #pragma unroll
        for (int j = 0; j < 8; j++) {
            lo[j] = __uint_as_float((unsigned)(acc2[i2][j]));
            hi[j] = __uint_as_float((unsigned)(acc2[i2][j] >> 32));
        }
        #pragma unroll
        for (int half = 0; half < 2; half++) {
            const float* accr = half ? hi : lo;
            size_t row = (size_t)(bm + ty * 8 + i2 * 2 + half);
            float* cp = C + row * N + bn + tx * 8;
            float4 v0, v1;
            v0.x = __fadd_rn(accr[0], bb[0]); v0.y = __fadd_rn(accr[1], bb[1]);
            v0.z = __fadd_rn(accr[2], bb[2]); v0.w = __fadd_rn(accr[3], bb[3]);
            v1.x = __fadd_rn(accr[4], bb[4]); v1.y = __fadd_rn(accr[5], bb[5]);
            v1.z = __fadd_rn(accr[6], bb[6]); v1.w = __fadd_rn(accr[7], bb[7]);
            if (RELU) {
                v0.x = fmaxf(v0.x, 0.f); v0.y = fmaxf(v0.y, 0.f);
                v0.z = fmaxf(v0.z, 0.f); v0.w = fmaxf(v0.w, 0.f);
                v1.x = fmaxf(v1.x, 0.f); v1.y = fmaxf(v1.y, 0.f);
                v1.z = fmaxf(v1.z, 0.f); v1.w = fmaxf(v1.w, 0.f);
            }
            *(float4*)cp = v0;
            *(float4*)(cp + 4) = v1;
        }
    }
}

// ---------------------------------------------------------------------------
// VQ kernel: FROZEN per-element numerics, FFMA2-packed (2 codes per lane).
// Extra: gathers zq bf16 hi/lo copies from pre-split codebook.
// ---------------------------------------------------------------------------
__global__ __launch_bounds__(256)
void vq_kernel(const float* __restrict__ Z, const float* __restrict__ emb,
               const float* __restrict__ Bk,
               const bf16* __restrict__ ehi, const bf16* __restrict__ elo,
               float* __restrict__ zq, bf16* __restrict__ zqhi,
               bf16* __restrict__ zqlo, float* __restrict__ idx_out)
{
    __shared__ float z_s[32][DDIM];
    __shared__ __align__(16) float e_s[DDIM][128];
    __shared__ float bk_s[128];

    const int tid  = threadIdx.x;
    const int lane = tid & 31;
    const int warp = tid >> 5;
    const size_t row0 = (size_t)blockIdx.x * 32;
    const int r0 = warp * 4;

    {
        const float4* zg = (const float4*)(Z + row0 * DDIM);
        float4* zs = (float4*)z_s;
        zs[tid]       = zg[tid];
        zs[tid + 256] = zg[tid + 256];
    }
    __syncthreads();

    float Ar[4];
    #pragma unroll
    for (int rr = 0; rr < 4; rr++) {
        const float* zp = z_s[r0 + rr];
        float z0 = zp[lane], z1 = zp[lane + 32];
        float p = __fadd_rn(__fmul_rn(z0, z0), __fmul_rn(z1, z1));
        #pragma unroll
        for (int off = 16; off > 0; off >>= 1)
            p = __fadd_rn(p, __shfl_down_sync(0xffffffffu, p, off));
        Ar[rr] = __shfl_sync(0xffffffffu, p, 0);
    }

    float best_d[4];
    int   best_k[4];
    #pragma unroll
    for (int r = 0; r < 4; r++) { best_d[r] = 3.4e38f; best_k[r] = 0; }

    for (int c0 = 0; c0 < KCODES; c0 += 128) {
        __syncthreads();
        {
            int kk = tid >> 1;
            int d0 = (tid & 1) * 32;
            const float* ep = emb + (size_t)(c0 + kk) * DDIM + d0;
            #pragma unroll
            for (int i = 0; i < 32; i += 4) {
                float4 v = *(const float4*)(ep + i);
                e_s[d0 + i + 0][kk] = v.x;
                e_s[d0 + i + 1][kk] = v.y;
                e_s[d0 + i + 2][kk] = v.z;
                e_s[d0 + i + 3][kk] = v.w;
            }
            if (tid < 128) bk_s[tid] = Bk[c0 + tid];
        }
        __syncthreads();

        ull accL[4][2], accH[4][2];
        #pragma unroll
        for (int r = 0; r < 4; r++)
            #pragma unroll
            for (int s = 0; s < 2; s++) { accL[r][s] = 0ull; accH[r][s] = 0ull; }

        #pragma unroll
        for (int d4 = 0; d4 < DDIM / 2; d4 += 4) {
            float4 zr[4];
            #pragma unroll
            for (int r = 0; r < 4; r++)
                zr[r] = *(const float4*)&z_s[r0 + r][d4];
            #pragma unroll
            for (int dd = 0; dd < 4; dd++) {
                int d = d4 + dd;
                ull ev0 = *(const ull*)&e_s[d][2 * lane];
                ull ev1 = *(const ull*)&e_s[d][64 + 2 * lane];
                #pragma unroll
                for (int r = 0; r < 4; r++) {
                    float zf = (dd == 0) ? zr[r].x : (dd == 1) ? zr[r].y
                             : (dd == 2) ? zr[r].z : zr[r].w;
                    ull zd = pack_dup(__float_as_uint(zf));
                    ffma2(accL[r][0], zd, ev0);
                    ffma2(accL[r][1], zd, ev1);
                }
            }
        }
        #pragma unroll
        for (int d4 = DDIM / 2; d4 < DDIM; d4 += 4) {
            float4 zr[4];
            #pragma unroll
            for (int r = 0; r < 4; r++)
                zr[r] = *(const float4*)&z_s[r0 + r][d4];
            #pragma unroll
            for (int dd = 0; dd < 4; dd++) {
                int d = d4 + dd;
                ull ev0 = *(const ull*)&e_s[d][2 * lane];
                ull ev1 = *(const ull*)&e_s[d][64 + 2 * lane];
                #pragma unroll
                for (int r = 0; r < 4; r++) {
                    float zf = (dd == 0) ? zr[r].x : (dd == 1) ? zr[r].y
                             : (dd == 2) ? zr[r].z : zr[r].w;
                    ull zd = pack_dup(__float_as_uint(zf));
                    ffma2(accH[r][0], zd, ev0);
                    ffma2(accH[r][1], zd, ev1);
                }
            }
        }

        #pragma unroll
        for (int r = 0; r < 4; r++) {
            #pragma unroll
            for (int s = 0; s < 2; s++) {
                #pragma unroll
                for (int j = 0; j < 2; j++) {
                    float eL = __uint_as_float(j == 0 ? (unsigned)accL[r][s]
                                                      : (unsigned)(accL[r][s] >> 32));
                    float eH = __uint_as_float(j == 0 ? (unsigned)accH[r][s]
                                                      : (unsigned)(accH[r][s] >> 32));
                    int kc = s * 64 + 2 * lane + j;
                    float E  = __fadd_rn(eL, eH);
                    float t  = __fadd_rn(Ar[r], bk_s[kc]);
                    float ds = __fadd_rn(t, -2.0f * E);
                    int k = c0 + kc;
                    if (ds < best_d[r]) { best_d[r] = ds; best_k[r] = k; }
                }
            }
        }
    }

    #pragma unroll
    for (int r = 0; r < 4; r++) {
        float bd = best_d[r];
        int   bk = best_k[r];
        #pragma unroll
        for (int off = 16; off > 0; off >>= 1) {
            float od = __shfl_down_sync(0xffffffffu, bd, off);
            int   ok = __shfl_down_sync(0xffffffffu, bk, off);
            if (od < bd || (od == bd && ok < bk)) { bd = od; bk = ok; }
        }
        bk = __shfl_sync(0xffffffffu, bk, 0);

        size_t grow = row0 + (size_t)warp * 4 + r;
        zq[grow * DDIM + lane]      = emb[(size_t)bk * DDIM + lane];
        zq[grow * DDIM + 32 + lane] = emb[(size_t)bk * DDIM + 32 + lane];
        zqhi[grow * DDIM + lane]      = ehi[bk * DDIM + lane];
        zqhi[grow * DDIM + 32 + lane] = ehi[bk * DDIM + 32 + lane];
        zqlo[grow * DDIM + lane]      = elo[bk * DDIM + lane];
        zqlo[grow * DDIM + 32 + lane] = elo[bk * DDIM + 32 + lane];
        if (lane == 0) idx_out[grow] = (float)bk;
    }
}

// ---------------------------------------------------------------------------
extern "C" void kernel_launch(void* const* d_in, const int* in_sizes, int n_in,
                              void* d_out, int out_size)
{
    const float* x   = (const float*)d_in[0];
    const float* W1  = (const float*)d_in[1];
    const float* b1  = (const float*)d_in[2];
    const float* W2  = (const float*)d_in[3];
    const float* b2  = (const float*)d_in[4];
    const float* emb = (const float*)d_in[5];
    const float* W3  = (const float*)d_in[6];
    const float* b3  = (const float*)d_in[7];
    const float* W4  = (const float*)d_in[8];
    const float* b4  = (const float*)d_in[9];

    float* out     = (float*)d_out;
    float* x_recon = out;
    float* z       = out + (size_t)B_ * IN_DIM;
    float* zq      = z   + (size_t)B_ * (LLAT * DDIM);
    float* idxf    = zq  + (size_t)B_ * (LLAT * DDIM);

    float *h, *Bk;
    bf16 *zqhi, *zqlo, *h2hi, *h2lo, *w3hi, *w3lo, *w4hi, *w4lo, *ehi, *elo;
    cudaGetSymbolAddress((void**)&h,    g_h);
    cudaGetSymbolAddress((void**)&Bk,   g_Bk);
    cudaGetSymbolAddress((void**)&zqhi, g_zqhi);
    cudaGetSymbolAddress((void**)&zqlo, g_zqlo);
    cudaGetSymbolAddress((void**)&h2hi, g_h2hi);
    cudaGetSymbolAddress((void**)&h2lo, g_h2lo);
    cudaGetSymbolAddress((void**)&w3hi, g_w3hi);
    cudaGetSymbolAddress((void**)&w3lo, g_w3lo);
    cudaGetSymbolAddress((void**)&w4hi, g_w4hi);
    cudaGetSymbolAddress((void**)&w4lo, g_w4lo);
    cudaGetSymbolAddress((void**)&ehi,  g_ehi);
    cudaGetSymbolAddress((void**)&elo,  g_elo);

    // prep (input-only dependent)
    bk_kernel<<<(KCODES * 32 + 255) / 256, 256>>>(emb, Bk);
    splitf<<<(KCODES * DDIM) / 1024, 256>>>(emb, ehi, elo);
    splitf<<<((size_t)HID * HID) / 1024, 256>>>(W3, w3hi, w3lo);
    splitf<<<((size_t)HID * IN_DIM) / 1024, 256>>>(W4, w4hi, w4lo);

    // encoder (bit-frozen)
    sgemm<true ><<<dim3(HID / 128, B_ / 128), 256>>>(x, W1, b1, h, B_, HID, IN_DIM);
    sgemm<false><<<dim3(HID / 128, B_ / 128), 256>>>(h, W2, b2, z, B_, HID, HID);
    vq_kernel<<<(B_ * LLAT) / 32, 256>>>(z, emb, Bk, ehi, elo, zq, zqhi, zqlo, idxf);

    // decoder (wmma bf16x3): h2 = relu(zq@W3+b3) -> fp32 in g_h, then split
    gemm_wmma<true ><<<dim3(HID / 128, B_ / 128), 256>>>(
        zqhi, zqlo, w3hi, w3lo, b3, h, HID, HID);
    splitf<<<((size_t)B_ * HID) / 1024, 256>>>(h, h2hi, h2lo);
    gemm_wmma<false><<<dim3(IN_DIM / 128, B_ / 128), 256>>>(
        h2hi, h2lo, w4hi, w4lo, b4, x_recon, IN_DIM, HID);
}